// round 1
// baseline (speedup 1.0000x reference)
#include <cuda_runtime.h>
#include <cuda_bf16.h>
#include <cstdint>
#include <cstdio>

// ---------------- problem constants ----------------
#define B_SZ 2
#define S_SZ 1024
#define D_SZ 1024
#define D_INNER 2048
#define HEADDIM 64
#define NHEADS 32
#define D_STATE 64
#define D_CONV 4
#define CONV_DIM (D_INNER + 2 * D_STATE)       // 2176
#define D_IN_PROJ (2 * D_INNER + 2 * D_STATE + NHEADS)  // 4256
#define H_MLP 8192
#define H_MLP2 4096
#define ROWS (B_SZ * S_SZ)                      // 2048

// ---------------- scratch (device globals; no allocation allowed) ----------------
__device__ float g_zxbcdt[ROWS * D_IN_PROJ];    // 34.9 MB
__device__ float g_xbc[ROWS * CONV_DIM];        // 17.8 MB  (post conv+silu)
__device__ float g_dt[ROWS * NHEADS];
__device__ float g_dA[ROWS * NHEADS];
__device__ float g_y[ROWS * D_INNER];           // scan output
__device__ float g_yg[ROWS * D_INNER];          // gated+rms'd
__device__ float g_x1[ROWS * D_SZ];             // x + mamba(x)
__device__ float g_xn[ROWS * D_SZ];             // rms(x1)
__device__ float g_h1[ROWS * H_MLP];            // fc1 out
__device__ float g_min[ROWS * H_MLP2];          // glu out

__device__ __forceinline__ float silu_f(float v) {
    return v / (1.f + __expf(-v));
}

// ---------------- generic fp32 SGEMM: C[M,N] = A[M,K] @ W[N,K]^T (+ addend) ----------------
// BM=BN=128, BK=8, 256 threads, 8x8 per thread. M must be multiple of 128,
// K multiple of 8, N multiple of 8 (bounds-checked per 128-tile).
#define BM 128
#define BN 128
#define BK 8
#define TM 8
#define TN 8

__global__ __launch_bounds__(256) void sgemm_kernel(
    const float* __restrict__ A, const float* __restrict__ W,
    const float* __restrict__ addend, float* __restrict__ C,
    int M, int N, int K)
{
    __shared__ float As[BK][BM];
    __shared__ float Bs[BK][BN];

    const int tid = threadIdx.x;
    const int bm = blockIdx.y * BM;
    const int bn = blockIdx.x * BN;

    const int lrow = tid >> 1;          // 0..127
    const int lcol = (tid & 1) * 4;     // 0 or 4

    const int ty = tid >> 4;            // 0..15
    const int tx = tid & 15;            // 0..15

    float acc[TM][TN];
#pragma unroll
    for (int i = 0; i < TM; i++)
#pragma unroll
        for (int j = 0; j < TN; j++) acc[i][j] = 0.f;

    const bool wrow_ok = (bn + lrow) < N;

    for (int k0 = 0; k0 < K; k0 += BK) {
        float4 av = *reinterpret_cast<const float4*>(&A[(size_t)(bm + lrow) * K + k0 + lcol]);
        float4 bv = make_float4(0.f, 0.f, 0.f, 0.f);
        if (wrow_ok)
            bv = *reinterpret_cast<const float4*>(&W[(size_t)(bn + lrow) * K + k0 + lcol]);

        As[lcol + 0][lrow] = av.x;
        As[lcol + 1][lrow] = av.y;
        As[lcol + 2][lrow] = av.z;
        As[lcol + 3][lrow] = av.w;
        Bs[lcol + 0][lrow] = bv.x;
        Bs[lcol + 1][lrow] = bv.y;
        Bs[lcol + 2][lrow] = bv.z;
        Bs[lcol + 3][lrow] = bv.w;
        __syncthreads();

#pragma unroll
        for (int k = 0; k < BK; k++) {
            float ar[TM], br[TN];
#pragma unroll
            for (int i = 0; i < TM; i++) ar[i] = As[k][ty * TM + i];
#pragma unroll
            for (int j = 0; j < TN; j++) br[j] = Bs[k][tx * TN + j];
#pragma unroll
            for (int i = 0; i < TM; i++)
#pragma unroll
                for (int j = 0; j < TN; j++)
                    acc[i][j] = fmaf(ar[i], br[j], acc[i][j]);
        }
        __syncthreads();
    }

#pragma unroll
    for (int i = 0; i < TM; i++) {
        const int row = bm + ty * TM + i;
#pragma unroll
        for (int j = 0; j < TN; j += 4) {
            const int col = bn + tx * TN + j;
            if (col < N) {
                float4 v = make_float4(acc[i][j], acc[i][j + 1], acc[i][j + 2], acc[i][j + 3]);
                if (addend) {
                    const float4 a = *reinterpret_cast<const float4*>(&addend[(size_t)row * N + col]);
                    v.x += a.x; v.y += a.y; v.z += a.z; v.w += a.w;
                }
                *reinterpret_cast<float4*>(&C[(size_t)row * N + col]) = v;
            }
        }
    }
}

// ---------------- causal depthwise conv (k=4) + bias + silu ----------------
__global__ void conv_silu_kernel(const float* __restrict__ conv_w,
                                 const float* __restrict__ conv_b)
{
    const int idx = blockIdx.x * blockDim.x + threadIdx.x;
    if (idx >= ROWS * CONV_DIM) return;
    const int c = idx % CONV_DIM;
    const int bs = idx / CONV_DIM;
    const int s = bs % S_SZ;
    const int b = bs / S_SZ;

    float acc = conv_b[c];
#pragma unroll
    for (int k = 0; k < D_CONV; k++) {
        const int ss = s - (D_CONV - 1) + k;
        if (ss >= 0)
            acc = fmaf(g_zxbcdt[(size_t)(b * S_SZ + ss) * D_IN_PROJ + D_INNER + c],
                       conv_w[c * D_CONV + k], acc);
    }
    g_xbc[idx] = silu_f(acc);
}

// ---------------- dt = softplus(dt_raw + dt_bias), dA = exp(-exp(A_log)*dt) ----------------
__global__ void dt_kernel(const float* __restrict__ dt_bias,
                          const float* __restrict__ A_log)
{
    const int idx = blockIdx.x * blockDim.x + threadIdx.x;
    if (idx >= ROWS * NHEADS) return;
    const int h = idx % NHEADS;
    const int r = idx / NHEADS;
    float x = g_zxbcdt[(size_t)r * D_IN_PROJ + (D_IN_PROJ - NHEADS) + h] + dt_bias[h];
    float dt = (x > 20.f) ? x : log1pf(expf(x));
    g_dt[idx] = dt;
    g_dA[idx] = expf(-expf(A_log[h]) * dt);
}

// ---------------- sequential SSM scan ----------------
// grid: 256 blocks = (b, h, p_chunk of 16); block: 1024 threads = 16 p x 64 n.
__global__ __launch_bounds__(1024) void scan_kernel()
{
    const int pc = blockIdx.x & 3;
    const int h  = (blockIdx.x >> 2) & (NHEADS - 1);
    const int b  = blockIdx.x >> 7;

    const int tid  = threadIdx.x;
    const int n    = tid & 63;
    const int pl   = tid >> 6;       // 0..15
    const int lane = tid & 31;
    const int half = (n >= 32) ? 1 : 0;

    __shared__ float sB[D_STATE], sC[D_STATE], sx[16];
    __shared__ float sy[16][2];
    __shared__ float sdt, sdA;

    float hst = 0.f;

    for (int s = 0; s < S_SZ; s++) {
        const float* row = g_xbc + (size_t)(b * S_SZ + s) * CONV_DIM;
        if (tid < 64)        sB[tid]        = row[D_INNER + tid];
        else if (tid < 128)  sC[tid - 64]   = row[D_INNER + D_STATE + (tid - 64)];
        else if (tid < 144)  sx[tid - 128]  = row[h * HEADDIM + pc * 16 + (tid - 128)];
        else if (tid == 144) {
            const int i = (b * S_SZ + s) * NHEADS + h;
            sdt = g_dt[i];
            sdA = g_dA[i];
        }
        __syncthreads();

        hst = fmaf(hst, sdA, (sdt * sx[pl]) * sB[n]);
        float part = hst * sC[n];
        part += __shfl_down_sync(0xffffffffu, part, 16);
        part += __shfl_down_sync(0xffffffffu, part, 8);
        part += __shfl_down_sync(0xffffffffu, part, 4);
        part += __shfl_down_sync(0xffffffffu, part, 2);
        part += __shfl_down_sync(0xffffffffu, part, 1);
        if (lane == 0) sy[pl][half] = part;
        __syncthreads();

        if (tid < 16)
            g_y[((size_t)(b * S_SZ + s) * NHEADS + h) * HEADDIM + pc * 16 + tid] =
                sy[tid][0] + sy[tid][1];
    }
}

// ---------------- gate: y = rms((y + D*xs) * silu(z)) * ssm_norm_w ----------------
__global__ __launch_bounds__(256) void gate_rms_kernel(const float* __restrict__ Dp,
                                                       const float* __restrict__ normw)
{
    const int row = blockIdx.x;
    const int tid = threadIdx.x;

    const float* yr = g_y      + (size_t)row * D_INNER;
    const float* xb = g_xbc    + (size_t)row * CONV_DIM;
    const float* zr = g_zxbcdt + (size_t)row * D_IN_PROJ;

    float vals[8];
    float ss = 0.f;
#pragma unroll
    for (int i = 0; i < 8; i++) {
        const int c = tid + i * 256;
        float v = fmaf(Dp[c >> 6], xb[c], yr[c]);
        v *= silu_f(zr[c]);
        vals[i] = v;
        ss = fmaf(v, v, ss);
    }
    __shared__ float red[32];
#pragma unroll
    for (int o = 16; o > 0; o >>= 1) ss += __shfl_down_sync(0xffffffffu, ss, o);
    if ((tid & 31) == 0) red[tid >> 5] = ss;
    __syncthreads();
    if (tid < 32) {
        float v = (tid < 8) ? red[tid] : 0.f;
#pragma unroll
        for (int o = 4; o > 0; o >>= 1) v += __shfl_down_sync(0xffffffffu, v, o);
        if (tid == 0) red[0] = v;
    }
    __syncthreads();
    const float inv = rsqrtf(red[0] / (float)D_INNER + 1e-5f);
#pragma unroll
    for (int i = 0; i < 8; i++) {
        const int c = tid + i * 256;
        g_yg[(size_t)row * D_INNER + c] = vals[i] * inv * normw[c];
    }
}

// ---------------- rms over D: xn = rms(x1) * rms_w ----------------
__global__ __launch_bounds__(256) void rms_kernel(const float* __restrict__ w)
{
    const int row = blockIdx.x;
    const int tid = threadIdx.x;
    const float* xr = g_x1 + (size_t)row * D_SZ;

    float vals[4];
    float ss = 0.f;
#pragma unroll
    for (int i = 0; i < 4; i++) {
        const int c = tid + i * 256;
        vals[i] = xr[c];
        ss = fmaf(vals[i], vals[i], ss);
    }
    __shared__ float red[32];
#pragma unroll
    for (int o = 16; o > 0; o >>= 1) ss += __shfl_down_sync(0xffffffffu, ss, o);
    if ((tid & 31) == 0) red[tid >> 5] = ss;
    __syncthreads();
    if (tid < 32) {
        float v = (tid < 8) ? red[tid] : 0.f;
#pragma unroll
        for (int o = 4; o > 0; o >>= 1) v += __shfl_down_sync(0xffffffffu, v, o);
        if (tid == 0) red[0] = v;
    }
    __syncthreads();
    const float inv = rsqrtf(red[0] / (float)D_SZ + 1e-5f);
#pragma unroll
    for (int i = 0; i < 4; i++) {
        const int c = tid + i * 256;
        g_xn[(size_t)row * D_SZ + c] = vals[i] * inv * w[c];
    }
}

// ---------------- GLU: m_in = a * silu(g) ----------------
__global__ void glu_kernel()
{
    const int idx = blockIdx.x * blockDim.x + threadIdx.x;
    if (idx >= ROWS * H_MLP2) return;
    const int j = idx % H_MLP2;
    const int r = idx / H_MLP2;
    const float a = g_h1[(size_t)r * H_MLP + j];
    const float g = g_h1[(size_t)r * H_MLP + H_MLP2 + j];
    g_min[idx] = a * silu_f(g);
}

// ---------------- launch ----------------
extern "C" void kernel_launch(void* const* d_in, const int* in_sizes, int n_in,
                              void* d_out, int out_size)
{
    const float* x          = (const float*)d_in[0];
    const float* in_proj_w  = (const float*)d_in[1];
    const float* conv_w     = (const float*)d_in[2];
    const float* conv_b     = (const float*)d_in[3];
    const float* dt_bias    = (const float*)d_in[4];
    const float* A_log      = (const float*)d_in[5];
    const float* Dp         = (const float*)d_in[6];
    const float* ssm_norm_w = (const float*)d_in[7];
    const float* out_proj_w = (const float*)d_in[8];
    const float* rms_w      = (const float*)d_in[9];
    const float* fc1_w      = (const float*)d_in[10];
    const float* fc2_w      = (const float*)d_in[11];
    float* out = (float*)d_out;

    float *p_zx, *p_yg, *p_x1, *p_xn, *p_h1, *p_min;
    cudaGetSymbolAddress((void**)&p_zx,  g_zxbcdt);
    cudaGetSymbolAddress((void**)&p_yg,  g_yg);
    cudaGetSymbolAddress((void**)&p_x1,  g_x1);
    cudaGetSymbolAddress((void**)&p_xn,  g_xn);
    cudaGetSymbolAddress((void**)&p_h1,  g_h1);
    cudaGetSymbolAddress((void**)&p_min, g_min);

    // 1) in_proj: zxbcdt[2048,4256] = x @ in_proj_w^T
    {
        dim3 grid((D_IN_PROJ + BN - 1) / BN, ROWS / BM);
        sgemm_kernel<<<grid, 256>>>(x, in_proj_w, nullptr, p_zx, ROWS, D_IN_PROJ, D_SZ);
    }
    // 2) dt/dA
    dt_kernel<<<(ROWS * NHEADS + 255) / 256, 256>>>(dt_bias, A_log);
    // 3) conv + silu
    conv_silu_kernel<<<(ROWS * CONV_DIM + 255) / 256, 256>>>(conv_w, conv_b);
    // 4) scan
    scan_kernel<<<B_SZ * NHEADS * 4, 1024>>>();
    // 5) gate + rms(ssm_norm)
    gate_rms_kernel<<<ROWS, 256>>>(Dp, ssm_norm_w);
    // 6) out_proj + residual: x1 = x + yg @ out_proj_w^T
    {
        dim3 grid(D_SZ / BN, ROWS / BM);
        sgemm_kernel<<<grid, 256>>>(p_yg, out_proj_w, x, p_x1, ROWS, D_SZ, D_INNER);
    }
    // 7) rms
    rms_kernel<<<ROWS, 256>>>(rms_w);
    // 8) fc1: h1 = xn @ fc1_w^T
    {
        dim3 grid(H_MLP / BN, ROWS / BM);
        sgemm_kernel<<<grid, 256>>>(p_xn, fc1_w, nullptr, p_h1, ROWS, H_MLP, D_SZ);
    }
    // 9) GLU
    glu_kernel<<<(ROWS * H_MLP2 + 255) / 256, 256>>>();
    // 10) fc2 + residual: out = x1 + m_in @ fc2_w^T
    {
        dim3 grid(D_SZ / BN, ROWS / BM);
        sgemm_kernel<<<grid, 256>>>(p_min, fc2_w, p_x1, out, ROWS, D_SZ, H_MLP2);
    }
}

// round 2
// speedup vs baseline: 1.9957x; 1.9957x over previous
#include <cuda_runtime.h>
#include <cuda_bf16.h>
#include <cstdint>
#include <cstdio>

// ---------------- problem constants ----------------
#define B_SZ 2
#define S_SZ 1024
#define D_SZ 1024
#define D_INNER 2048
#define HEADDIM 64
#define NHEADS 32
#define D_STATE 64
#define D_CONV 4
#define CONV_DIM (D_INNER + 2 * D_STATE)       // 2176
#define D_IN_PROJ (2 * D_INNER + 2 * D_STATE + NHEADS)  // 4256
#define H_MLP 8192
#define H_MLP2 4096
#define ROWS (B_SZ * S_SZ)                      // 2048

// ---------------- scratch (device globals; no allocation allowed) ----------------
__device__ float g_zxbcdt[ROWS * D_IN_PROJ];
__device__ float g_xbc[ROWS * CONV_DIM];
__device__ float g_dt[ROWS * NHEADS];
__device__ float g_dA[ROWS * NHEADS];
__device__ float g_y[ROWS * D_INNER];
__device__ float g_yg[ROWS * D_INNER];
__device__ float g_x1[ROWS * D_SZ];
__device__ float g_xn[ROWS * D_SZ];
__device__ float g_h1[ROWS * H_MLP];
__device__ float g_min[ROWS * H_MLP2];

__device__ __forceinline__ float silu_f(float v) {
    return v / (1.f + __expf(-v));
}

__device__ __forceinline__ uint32_t f2tf32(float f) {
    uint32_t u;
    asm("cvt.rna.tf32.f32 %0, %1;" : "=r"(u) : "f"(f));
    return u;
}

// ---------------- TF32 tensor-core GEMM ----------------
// C[M,N] = A[M,K] @ W[N,K]^T (+ addend).  M % 128 == 0, K % 16 == 0, N even.
// 128x128 CTA tile, 8 warps (2m x 4n), warp tile 64x32, mma.m16n8k8.tf32.
#define TBK 16
#define SSTRIDE 20   // smem floats per row (16 + 4 pad -> conflict-free frag loads)

__global__ __launch_bounds__(256) void tf32_gemm_kernel(
    const float* __restrict__ A, const float* __restrict__ W,
    const float* __restrict__ addend, float* __restrict__ C,
    int M, int N, int K)
{
    __shared__ uint32_t As[128 * SSTRIDE];
    __shared__ uint32_t Bs[128 * SSTRIDE];

    const int tid = threadIdx.x;
    const int bm = blockIdx.y * 128;
    const int bn = blockIdx.x * 128;

    const int warp = tid >> 5;
    const int lane = tid & 31;
    const int g  = lane >> 2;   // group id 0..7
    const int t4 = lane & 3;    // thread-in-group 0..3

    const int warp_m = (warp >> 2) * 64;   // 0 or 64
    const int warp_n = (warp & 3) * 32;    // 0,32,64,96

    // load mapping: 2 passes of 64 rows; 4 threads per row, one float4 each
    const int lr  = tid >> 2;          // 0..63
    const int lc  = (tid & 3) * 4;     // 0,4,8,12

    const float* Arow0 = A + (size_t)(bm + lr) * K + lc;
    const float* Arow1 = A + (size_t)(bm + 64 + lr) * K + lc;
    int wr0 = bn + lr;       if (wr0 > N - 1) wr0 = N - 1;
    int wr1 = bn + 64 + lr;  if (wr1 > N - 1) wr1 = N - 1;
    const float* Wrow0 = W + (size_t)wr0 * K + lc;
    const float* Wrow1 = W + (size_t)wr1 * K + lc;

    float acc[4][4][4];
#pragma unroll
    for (int i = 0; i < 4; i++)
#pragma unroll
        for (int j = 0; j < 4; j++)
#pragma unroll
            for (int r = 0; r < 4; r++) acc[i][j][r] = 0.f;

    const int ksteps = K / TBK;

    // prefetch tile 0
    float4 la0 = *reinterpret_cast<const float4*>(Arow0);
    float4 la1 = *reinterpret_cast<const float4*>(Arow1);
    float4 lb0 = *reinterpret_cast<const float4*>(Wrow0);
    float4 lb1 = *reinterpret_cast<const float4*>(Wrow1);

    for (int kt = 0; kt < ksteps; kt++) {
        // store staged tile to smem (tf32-rounded)
        {
            uint4 ua0 = make_uint4(f2tf32(la0.x), f2tf32(la0.y), f2tf32(la0.z), f2tf32(la0.w));
            uint4 ua1 = make_uint4(f2tf32(la1.x), f2tf32(la1.y), f2tf32(la1.z), f2tf32(la1.w));
            uint4 ub0 = make_uint4(f2tf32(lb0.x), f2tf32(lb0.y), f2tf32(lb0.z), f2tf32(lb0.w));
            uint4 ub1 = make_uint4(f2tf32(lb1.x), f2tf32(lb1.y), f2tf32(lb1.z), f2tf32(lb1.w));
            *reinterpret_cast<uint4*>(&As[lr * SSTRIDE + lc])        = ua0;
            *reinterpret_cast<uint4*>(&As[(64 + lr) * SSTRIDE + lc]) = ua1;
            *reinterpret_cast<uint4*>(&Bs[lr * SSTRIDE + lc])        = ub0;
            *reinterpret_cast<uint4*>(&Bs[(64 + lr) * SSTRIDE + lc]) = ub1;
        }
        __syncthreads();

        // prefetch next tile (overlaps mma below)
        if (kt + 1 < ksteps) {
            const int ko = (kt + 1) * TBK;
            la0 = *reinterpret_cast<const float4*>(Arow0 + ko);
            la1 = *reinterpret_cast<const float4*>(Arow1 + ko);
            lb0 = *reinterpret_cast<const float4*>(Wrow0 + ko);
            lb1 = *reinterpret_cast<const float4*>(Wrow1 + ko);
        }

#pragma unroll
        for (int kk = 0; kk < TBK; kk += 8) {
            uint32_t af[4][4];
            uint32_t bf[4][2];
#pragma unroll
            for (int mt = 0; mt < 4; mt++) {
                const int r0 = warp_m + mt * 16 + g;
                af[mt][0] = As[r0 * SSTRIDE + kk + t4];
                af[mt][1] = As[(r0 + 8) * SSTRIDE + kk + t4];
                af[mt][2] = As[r0 * SSTRIDE + kk + t4 + 4];
                af[mt][3] = As[(r0 + 8) * SSTRIDE + kk + t4 + 4];
            }
#pragma unroll
            for (int nt = 0; nt < 4; nt++) {
                const int c0 = warp_n + nt * 8 + g;
                bf[nt][0] = Bs[c0 * SSTRIDE + kk + t4];
                bf[nt][1] = Bs[c0 * SSTRIDE + kk + t4 + 4];
            }
#pragma unroll
            for (int mt = 0; mt < 4; mt++)
#pragma unroll
                for (int nt = 0; nt < 4; nt++) {
                    asm volatile(
                        "mma.sync.aligned.m16n8k8.row.col.f32.tf32.tf32.f32 "
                        "{%0,%1,%2,%3}, {%4,%5,%6,%7}, {%8,%9}, {%0,%1,%2,%3};"
                        : "+f"(acc[mt][nt][0]), "+f"(acc[mt][nt][1]),
                          "+f"(acc[mt][nt][2]), "+f"(acc[mt][nt][3])
                        : "r"(af[mt][0]), "r"(af[mt][1]), "r"(af[mt][2]), "r"(af[mt][3]),
                          "r"(bf[nt][0]), "r"(bf[nt][1]));
                }
        }
        __syncthreads();
    }

    // epilogue
#pragma unroll
    for (int mt = 0; mt < 4; mt++) {
        const int row0 = bm + warp_m + mt * 16 + g;
#pragma unroll
        for (int nt = 0; nt < 4; nt++) {
            const int col = bn + warp_n + nt * 8 + 2 * t4;
            if (col < N) {
                float2 v0 = make_float2(acc[mt][nt][0], acc[mt][nt][1]);
                float2 v1 = make_float2(acc[mt][nt][2], acc[mt][nt][3]);
                if (addend) {
                    const float2 a0 = *reinterpret_cast<const float2*>(&addend[(size_t)row0 * N + col]);
                    const float2 a1 = *reinterpret_cast<const float2*>(&addend[(size_t)(row0 + 8) * N + col]);
                    v0.x += a0.x; v0.y += a0.y;
                    v1.x += a1.x; v1.y += a1.y;
                }
                *reinterpret_cast<float2*>(&C[(size_t)row0 * N + col]) = v0;
                *reinterpret_cast<float2*>(&C[(size_t)(row0 + 8) * N + col]) = v1;
            }
        }
    }
}

// ---------------- causal depthwise conv (k=4) + bias + silu ----------------
__global__ void conv_silu_kernel(const float* __restrict__ conv_w,
                                 const float* __restrict__ conv_b)
{
    const int idx = blockIdx.x * blockDim.x + threadIdx.x;
    if (idx >= ROWS * CONV_DIM) return;
    const int c = idx % CONV_DIM;
    const int bs = idx / CONV_DIM;
    const int s = bs % S_SZ;
    const int b = bs / S_SZ;

    float acc = conv_b[c];
#pragma unroll
    for (int k = 0; k < D_CONV; k++) {
        const int ss = s - (D_CONV - 1) + k;
        if (ss >= 0)
            acc = fmaf(g_zxbcdt[(size_t)(b * S_SZ + ss) * D_IN_PROJ + D_INNER + c],
                       conv_w[c * D_CONV + k], acc);
    }
    g_xbc[idx] = silu_f(acc);
}

// ---------------- dt = softplus(dt_raw + dt_bias), dA = exp(-exp(A_log)*dt) ----------------
__global__ void dt_kernel(const float* __restrict__ dt_bias,
                          const float* __restrict__ A_log)
{
    const int idx = blockIdx.x * blockDim.x + threadIdx.x;
    if (idx >= ROWS * NHEADS) return;
    const int h = idx % NHEADS;
    const int r = idx / NHEADS;
    float x = g_zxbcdt[(size_t)r * D_IN_PROJ + (D_IN_PROJ - NHEADS) + h] + dt_bias[h];
    float dt = (x > 20.f) ? x : log1pf(expf(x));
    g_dt[idx] = dt;
    g_dA[idx] = expf(-expf(A_log[h]) * dt);
}

// ---------------- sequential SSM scan ----------------
__global__ __launch_bounds__(1024) void scan_kernel()
{
    const int pc = blockIdx.x & 3;
    const int h  = (blockIdx.x >> 2) & (NHEADS - 1);
    const int b  = blockIdx.x >> 7;

    const int tid  = threadIdx.x;
    const int n    = tid & 63;
    const int pl   = tid >> 6;
    const int lane = tid & 31;
    const int half = (n >= 32) ? 1 : 0;

    __shared__ float sB[D_STATE], sC[D_STATE], sx[16];
    __shared__ float sy[16][2];
    __shared__ float sdt, sdA;

    float hst = 0.f;

    for (int s = 0; s < S_SZ; s++) {
        const float* row = g_xbc + (size_t)(b * S_SZ + s) * CONV_DIM;
        if (tid < 64)        sB[tid]        = row[D_INNER + tid];
        else if (tid < 128)  sC[tid - 64]   = row[D_INNER + D_STATE + (tid - 64)];
        else if (tid < 144)  sx[tid - 128]  = row[h * HEADDIM + pc * 16 + (tid - 128)];
        else if (tid == 144) {
            const int i = (b * S_SZ + s) * NHEADS + h;
            sdt = g_dt[i];
            sdA = g_dA[i];
        }
        __syncthreads();

        hst = fmaf(hst, sdA, (sdt * sx[pl]) * sB[n]);
        float part = hst * sC[n];
        part += __shfl_down_sync(0xffffffffu, part, 16);
        part += __shfl_down_sync(0xffffffffu, part, 8);
        part += __shfl_down_sync(0xffffffffu, part, 4);
        part += __shfl_down_sync(0xffffffffu, part, 2);
        part += __shfl_down_sync(0xffffffffu, part, 1);
        if (lane == 0) sy[pl][half] = part;
        __syncthreads();

        if (tid < 16)
            g_y[((size_t)(b * S_SZ + s) * NHEADS + h) * HEADDIM + pc * 16 + tid] =
                sy[tid][0] + sy[tid][1];
    }
}

// ---------------- gate: y = rms((y + D*xs) * silu(z)) * ssm_norm_w ----------------
__global__ __launch_bounds__(256) void gate_rms_kernel(const float* __restrict__ Dp,
                                                       const float* __restrict__ normw)
{
    const int row = blockIdx.x;
    const int tid = threadIdx.x;

    const float* yr = g_y      + (size_t)row * D_INNER;
    const float* xb = g_xbc    + (size_t)row * CONV_DIM;
    const float* zr = g_zxbcdt + (size_t)row * D_IN_PROJ;

    float vals[8];
    float ss = 0.f;
#pragma unroll
    for (int i = 0; i < 8; i++) {
        const int c = tid + i * 256;
        float v = fmaf(Dp[c >> 6], xb[c], yr[c]);
        v *= silu_f(zr[c]);
        vals[i] = v;
        ss = fmaf(v, v, ss);
    }
    __shared__ float red[32];
#pragma unroll
    for (int o = 16; o > 0; o >>= 1) ss += __shfl_down_sync(0xffffffffu, ss, o);
    if ((tid & 31) == 0) red[tid >> 5] = ss;
    __syncthreads();
    if (tid < 32) {
        float v = (tid < 8) ? red[tid] : 0.f;
#pragma unroll
        for (int o = 4; o > 0; o >>= 1) v += __shfl_down_sync(0xffffffffu, v, o);
        if (tid == 0) red[0] = v;
    }
    __syncthreads();
    const float inv = rsqrtf(red[0] / (float)D_INNER + 1e-5f);
#pragma unroll
    for (int i = 0; i < 8; i++) {
        const int c = tid + i * 256;
        g_yg[(size_t)row * D_INNER + c] = vals[i] * inv * normw[c];
    }
}

// ---------------- rms over D: xn = rms(x1) * rms_w ----------------
__global__ __launch_bounds__(256) void rms_kernel(const float* __restrict__ w)
{
    const int row = blockIdx.x;
    const int tid = threadIdx.x;
    const float* xr = g_x1 + (size_t)row * D_SZ;

    float vals[4];
    float ss = 0.f;
#pragma unroll
    for (int i = 0; i < 4; i++) {
        const int c = tid + i * 256;
        vals[i] = xr[c];
        ss = fmaf(vals[i], vals[i], ss);
    }
    __shared__ float red[32];
#pragma unroll
    for (int o = 16; o > 0; o >>= 1) ss += __shfl_down_sync(0xffffffffu, ss, o);
    if ((tid & 31) == 0) red[tid >> 5] = ss;
    __syncthreads();
    if (tid < 32) {
        float v = (tid < 8) ? red[tid] : 0.f;
#pragma unroll
        for (int o = 4; o > 0; o >>= 1) v += __shfl_down_sync(0xffffffffu, v, o);
        if (tid == 0) red[0] = v;
    }
    __syncthreads();
    const float inv = rsqrtf(red[0] / (float)D_SZ + 1e-5f);
#pragma unroll
    for (int i = 0; i < 4; i++) {
        const int c = tid + i * 256;
        g_xn[(size_t)row * D_SZ + c] = vals[i] * inv * w[c];
    }
}

// ---------------- GLU: m_in = a * silu(g) ----------------
__global__ void glu_kernel()
{
    const int idx = blockIdx.x * blockDim.x + threadIdx.x;
    if (idx >= ROWS * H_MLP2) return;
    const int j = idx % H_MLP2;
    const int r = idx / H_MLP2;
    const float a = g_h1[(size_t)r * H_MLP + j];
    const float g = g_h1[(size_t)r * H_MLP + H_MLP2 + j];
    g_min[idx] = a * silu_f(g);
}

// ---------------- launch ----------------
extern "C" void kernel_launch(void* const* d_in, const int* in_sizes, int n_in,
                              void* d_out, int out_size)
{
    const float* x          = (const float*)d_in[0];
    const float* in_proj_w  = (const float*)d_in[1];
    const float* conv_w     = (const float*)d_in[2];
    const float* conv_b     = (const float*)d_in[3];
    const float* dt_bias    = (const float*)d_in[4];
    const float* A_log      = (const float*)d_in[5];
    const float* Dp         = (const float*)d_in[6];
    const float* ssm_norm_w = (const float*)d_in[7];
    const float* out_proj_w = (const float*)d_in[8];
    const float* rms_w      = (const float*)d_in[9];
    const float* fc1_w      = (const float*)d_in[10];
    const float* fc2_w      = (const float*)d_in[11];
    float* out = (float*)d_out;

    float *p_zx, *p_yg, *p_x1, *p_xn, *p_h1, *p_min;
    cudaGetSymbolAddress((void**)&p_zx,  g_zxbcdt);
    cudaGetSymbolAddress((void**)&p_yg,  g_yg);
    cudaGetSymbolAddress((void**)&p_x1,  g_x1);
    cudaGetSymbolAddress((void**)&p_xn,  g_xn);
    cudaGetSymbolAddress((void**)&p_h1,  g_h1);
    cudaGetSymbolAddress((void**)&p_min, g_min);

    // 1) in_proj: zxbcdt[2048,4256] = x @ in_proj_w^T
    {
        dim3 grid((D_IN_PROJ + 127) / 128, ROWS / 128);
        tf32_gemm_kernel<<<grid, 256>>>(x, in_proj_w, nullptr, p_zx, ROWS, D_IN_PROJ, D_SZ);
    }
    // 2) dt/dA
    dt_kernel<<<(ROWS * NHEADS + 255) / 256, 256>>>(dt_bias, A_log);
    // 3) conv + silu
    conv_silu_kernel<<<(ROWS * CONV_DIM + 255) / 256, 256>>>(conv_w, conv_b);
    // 4) scan
    scan_kernel<<<B_SZ * NHEADS * 4, 1024>>>();
    // 5) gate + rms(ssm_norm)
    gate_rms_kernel<<<ROWS, 256>>>(Dp, ssm_norm_w);
    // 6) out_proj + residual: x1 = x + yg @ out_proj_w^T
    {
        dim3 grid(D_SZ / 128, ROWS / 128);
        tf32_gemm_kernel<<<grid, 256>>>(p_yg, out_proj_w, x, p_x1, ROWS, D_SZ, D_INNER);
    }
    // 7) rms
    rms_kernel<<<ROWS, 256>>>(rms_w);
    // 8) fc1: h1 = xn @ fc1_w^T
    {
        dim3 grid(H_MLP / 128, ROWS / 128);
        tf32_gemm_kernel<<<grid, 256>>>(p_xn, fc1_w, nullptr, p_h1, ROWS, H_MLP, D_SZ);
    }
    // 9) GLU
    glu_kernel<<<(ROWS * H_MLP2 + 255) / 256, 256>>>();
    // 10) fc2 + residual: out = x1 + m_in @ fc2_w^T
    {
        dim3 grid(D_SZ / 128, ROWS / 128);
        tf32_gemm_kernel<<<grid, 256>>>(p_min, fc2_w, p_x1, out, ROWS, D_SZ, H_MLP2);
    }
}

// round 4
// speedup vs baseline: 2.0841x; 1.0443x over previous
#include <cuda_runtime.h>
#include <cuda_bf16.h>
#include <cstdint>
#include <cstdio>

// ---------------- problem constants ----------------
#define B_SZ 2
#define S_SZ 1024
#define D_SZ 1024
#define D_INNER 2048
#define HEADDIM 64
#define NHEADS 32
#define D_STATE 64
#define D_CONV 4
#define CONV_DIM (D_INNER + 2 * D_STATE)                 // 2176
#define D_IN_PROJ (2 * D_INNER + 2 * D_STATE + NHEADS)   // 4256
#define H_MLP 8192
#define H_MLP2 4096
#define ROWS (B_SZ * S_SZ)                               // 2048

// ---------------- scratch (device globals; no allocation allowed) ----------------
__device__ float g_zxbcdt[ROWS * D_IN_PROJ];
__device__ float g_xbc[ROWS * CONV_DIM];
__device__ float g_dt[ROWS * NHEADS];
__device__ float g_dA[ROWS * NHEADS];
__device__ float g_y[ROWS * D_INNER];
__device__ float g_yg[ROWS * D_INNER];
__device__ float g_x1[ROWS * D_SZ];
__device__ float g_xn[ROWS * D_SZ];
__device__ float g_h1[ROWS * H_MLP];
__device__ float g_min[ROWS * H_MLP2];
// tf32-rounded operand copies
__device__ float g_xc [ROWS * D_SZ];
__device__ float g_wip[D_IN_PROJ * D_SZ];
__device__ float g_wop[D_SZ * D_INNER];
__device__ float g_wf1[H_MLP * D_SZ];
__device__ float g_wf2[D_SZ * H_MLP2];

__device__ __forceinline__ float silu_f(float v) {
    return v / (1.f + __expf(-v));
}
__device__ __forceinline__ uint32_t f2tf32(float f) {
    uint32_t u;
    asm("cvt.rna.tf32.f32 %0, %1;" : "=r"(u) : "f"(f));
    return u;
}
__device__ __forceinline__ float rnd_tf32(float f) { return __uint_as_float(f2tf32(f)); }

__device__ __forceinline__ uint32_t smem_u32(const void* p) {
    uint32_t a;
    asm("{ .reg .u64 t; cvta.to.shared.u64 t, %1; cvt.u32.u64 %0, t; }" : "=r"(a) : "l"(p));
    return a;
}
__device__ __forceinline__ void cp_async16(uint32_t dst, const void* src) {
    asm volatile("cp.async.cg.shared.global [%0], [%1], 16;" :: "r"(dst), "l"(src));
}
#define CP_COMMIT() asm volatile("cp.async.commit_group;" ::: "memory")
#define CP_WAIT(n)  asm volatile("cp.async.wait_group %0;" :: "n"(n) : "memory")

// ---------------- pipelined tf32 mma.sync GEMM ----------------
// C[M,N] = A[M,K] @ W[N,K]^T (+ addend). A and W must be tf32-rounded already.
// 128x128 CTA tile, BK=16, 4-stage cp.async pipeline, 8 warps (2m x 4n),
// warp tile 64x32, mma.m16n8k8.tf32.
// M % 128 == 0, K % 16 == 0, N even (partial last N-tile handled).
#define GSTRIDE 20                    // smem words per row (16 data + 4 pad)
#define ASTG (128 * GSTRIDE)          // words per A stage  = 2560
#define STGW (2 * ASTG)               // words per stage    = 5120
#define NSTG 4
#define SMEM_WORDS (NSTG * STGW)      // 20480 words = 81920 B

__global__ __launch_bounds__(256, 2) void tf32_gemm_kernel(
    const float* __restrict__ A, const float* __restrict__ W,
    const float* __restrict__ addend, float* __restrict__ C,
    int M, int N, int K)
{
    extern __shared__ uint32_t sm[];
    const uint32_t sb = smem_u32(sm);

    const int tid = threadIdx.x;
    const int bm = blockIdx.y * 128;
    const int bn = blockIdx.x * 128;

    const int warp = tid >> 5;
    const int lane = tid & 31;
    const int g  = lane >> 2;
    const int t4 = lane & 3;
    const int warp_m = (warp >> 2) * 64;
    const int warp_n = (warp & 3) * 32;

    // load mapping: thread handles A rows {r, r+64} and W rows {r, r+64}, quad q
    const int lr = tid >> 2;            // 0..63
    const int q  = tid & 3;             // 16B chunk index

    const float* Ap0 = A + (size_t)(bm + lr) * K + q * 4;
    const float* Ap1 = A + (size_t)(bm + 64 + lr) * K + q * 4;
    int wr0 = bn + lr;      if (wr0 > N - 1) wr0 = N - 1;
    int wr1 = bn + 64 + lr; if (wr1 > N - 1) wr1 = N - 1;
    const float* Wp0 = W + (size_t)wr0 * K + q * 4;
    const float* Wp1 = W + (size_t)wr1 * K + q * 4;

    const uint32_t d0 = (uint32_t)lr * 80 + q * 16;          // bytes within stage
    const uint32_t d1 = d0 + 64 * 80;
    const int T = K / 16;

    float acc[4][4][4];
#pragma unroll
    for (int i = 0; i < 4; i++)
#pragma unroll
        for (int j = 0; j < 4; j++)
#pragma unroll
            for (int r = 0; r < 4; r++) acc[i][j][r] = 0.f;

    auto load_stage = [&](int j) {
        if (j < T) {
            const uint32_t base = sb + (j & (NSTG - 1)) * (STGW * 4);
            const int ko = j * 16;
            cp_async16(base + d0, Ap0 + ko);
            cp_async16(base + d1, Ap1 + ko);
            cp_async16(base + ASTG * 4 + d0, Wp0 + ko);
            cp_async16(base + ASTG * 4 + d1, Wp1 + ko);
        }
        CP_COMMIT();
    };

    load_stage(0);
    load_stage(1);
    load_stage(2);

    for (int kt = 0; kt < T; kt++) {
        CP_WAIT(2);
        __syncthreads();
        load_stage(kt + 3);

        const uint32_t* As = sm + (kt & (NSTG - 1)) * STGW;
        const uint32_t* Bs = As + ASTG;
#pragma unroll
        for (int kk = 0; kk < 16; kk += 8) {
            uint32_t af[4][4];
            uint32_t bf[4][2];
#pragma unroll
            for (int mt = 0; mt < 4; mt++) {
                const int r0 = warp_m + mt * 16 + g;
                af[mt][0] = As[r0 * GSTRIDE + kk + t4];
                af[mt][1] = As[(r0 + 8) * GSTRIDE + kk + t4];
                af[mt][2] = As[r0 * GSTRIDE + kk + t4 + 4];
                af[mt][3] = As[(r0 + 8) * GSTRIDE + kk + t4 + 4];
            }
#pragma unroll
            for (int nt = 0; nt < 4; nt++) {
                const int c0 = warp_n + nt * 8 + g;
                bf[nt][0] = Bs[c0 * GSTRIDE + kk + t4];
                bf[nt][1] = Bs[c0 * GSTRIDE + kk + t4 + 4];
            }
#pragma unroll
            for (int mt = 0; mt < 4; mt++)
#pragma unroll
                for (int nt = 0; nt < 4; nt++) {
                    asm volatile(
                        "mma.sync.aligned.m16n8k8.row.col.f32.tf32.tf32.f32 "
                        "{%0,%1,%2,%3}, {%4,%5,%6,%7}, {%8,%9}, {%0,%1,%2,%3};"
                        : "+f"(acc[mt][nt][0]), "+f"(acc[mt][nt][1]),
                          "+f"(acc[mt][nt][2]), "+f"(acc[mt][nt][3])
                        : "r"(af[mt][0]), "r"(af[mt][1]), "r"(af[mt][2]), "r"(af[mt][3]),
                          "r"(bf[nt][0]), "r"(bf[nt][1]));
                }
        }
    }

    // epilogue
#pragma unroll
    for (int mt = 0; mt < 4; mt++) {
        const int row0 = bm + warp_m + mt * 16 + g;
#pragma unroll
        for (int nt = 0; nt < 4; nt++) {
            const int col = bn + warp_n + nt * 8 + 2 * t4;
            if (col < N) {
                float2 v0 = make_float2(acc[mt][nt][0], acc[mt][nt][1]);
                float2 v1 = make_float2(acc[mt][nt][2], acc[mt][nt][3]);
                if (addend) {
                    const float2 a0 = *reinterpret_cast<const float2*>(&addend[(size_t)row0 * N + col]);
                    const float2 a1 = *reinterpret_cast<const float2*>(&addend[(size_t)(row0 + 8) * N + col]);
                    v0.x += a0.x; v0.y += a0.y;
                    v1.x += a1.x; v1.y += a1.y;
                }
                *reinterpret_cast<float2*>(&C[(size_t)row0 * N + col]) = v0;
                *reinterpret_cast<float2*>(&C[(size_t)(row0 + 8) * N + col]) = v1;
            }
        }
    }
}

// ---------------- tf32 rounding copy ----------------
__global__ void cvt_kernel(const float* __restrict__ in, float* __restrict__ out, int n4)
{
    const int i = blockIdx.x * blockDim.x + threadIdx.x;
    if (i >= n4) return;
    float4 v = reinterpret_cast<const float4*>(in)[i];
    v.x = rnd_tf32(v.x); v.y = rnd_tf32(v.y); v.z = rnd_tf32(v.z); v.w = rnd_tf32(v.w);
    reinterpret_cast<float4*>(out)[i] = v;
}

// ---------------- causal depthwise conv (k=4) + bias + silu ----------------
__global__ void conv_silu_kernel(const float* __restrict__ conv_w,
                                 const float* __restrict__ conv_b)
{
    const int idx = blockIdx.x * blockDim.x + threadIdx.x;
    if (idx >= ROWS * CONV_DIM) return;
    const int c = idx % CONV_DIM;
    const int bs = idx / CONV_DIM;
    const int s = bs % S_SZ;
    const int b = bs / S_SZ;

    float acc = conv_b[c];
#pragma unroll
    for (int k = 0; k < D_CONV; k++) {
        const int ss = s - (D_CONV - 1) + k;
        if (ss >= 0)
            acc = fmaf(g_zxbcdt[(size_t)(b * S_SZ + ss) * D_IN_PROJ + D_INNER + c],
                       conv_w[c * D_CONV + k], acc);
    }
    g_xbc[idx] = silu_f(acc);
}

// ---------------- dt/dA ----------------
__global__ void dt_kernel(const float* __restrict__ dt_bias,
                          const float* __restrict__ A_log)
{
    const int idx = blockIdx.x * blockDim.x + threadIdx.x;
    if (idx >= ROWS * NHEADS) return;
    const int h = idx % NHEADS;
    const int r = idx / NHEADS;
    float x = g_zxbcdt[(size_t)r * D_IN_PROJ + (D_IN_PROJ - NHEADS) + h] + dt_bias[h];
    float dt = (x > 20.f) ? x : log1pf(expf(x));
    g_dt[idx] = dt;
    g_dA[idx] = expf(-expf(A_log[h]) * dt);
}

// ---------------- sequential SSM scan ----------------
__global__ __launch_bounds__(1024) void scan_kernel()
{
    const int pc = blockIdx.x & 3;
    const int h  = (blockIdx.x >> 2) & (NHEADS - 1);
    const int b  = blockIdx.x >> 7;

    const int tid  = threadIdx.x;
    const int n    = tid & 63;
    const int pl   = tid >> 6;
    const int lane = tid & 31;
    const int half = (n >= 32) ? 1 : 0;

    __shared__ float sB[D_STATE], sC[D_STATE], sx[16];
    __shared__ float sy[16][2];
    __shared__ float sdt, sdA;

    float hst = 0.f;

    for (int s = 0; s < S_SZ; s++) {
        const float* row = g_xbc + (size_t)(b * S_SZ + s) * CONV_DIM;
        if (tid < 64)        sB[tid]        = row[D_INNER + tid];
        else if (tid < 128)  sC[tid - 64]   = row[D_INNER + D_STATE + (tid - 64)];
        else if (tid < 144)  sx[tid - 128]  = row[h * HEADDIM + pc * 16 + (tid - 128)];
        else if (tid == 144) {
            const int i = (b * S_SZ + s) * NHEADS + h;
            sdt = g_dt[i];
            sdA = g_dA[i];
        }
        __syncthreads();

        hst = fmaf(hst, sdA, (sdt * sx[pl]) * sB[n]);
        float part = hst * sC[n];
        part += __shfl_down_sync(0xffffffffu, part, 16);
        part += __shfl_down_sync(0xffffffffu, part, 8);
        part += __shfl_down_sync(0xffffffffu, part, 4);
        part += __shfl_down_sync(0xffffffffu, part, 2);
        part += __shfl_down_sync(0xffffffffu, part, 1);
        if (lane == 0) sy[pl][half] = part;
        __syncthreads();

        if (tid < 16)
            g_y[((size_t)(b * S_SZ + s) * NHEADS + h) * HEADDIM + pc * 16 + tid] =
                sy[tid][0] + sy[tid][1];
    }
}

// ---------------- gate: yg = rms((y + D*xs) * silu(z)) * w   (tf32-rounded out) ----------------
__global__ __launch_bounds__(256) void gate_rms_kernel(const float* __restrict__ Dp,
                                                       const float* __restrict__ normw)
{
    const int row = blockIdx.x;
    const int tid = threadIdx.x;

    const float* yr = g_y      + (size_t)row * D_INNER;
    const float* xb = g_xbc    + (size_t)row * CONV_DIM;
    const float* zr = g_zxbcdt + (size_t)row * D_IN_PROJ;

    float vals[8];
    float ss = 0.f;
#pragma unroll
    for (int i = 0; i < 8; i++) {
        const int c = tid + i * 256;
        float v = fmaf(Dp[c >> 6], xb[c], yr[c]);
        v *= silu_f(zr[c]);
        vals[i] = v;
        ss = fmaf(v, v, ss);
    }
    __shared__ float red[32];
#pragma unroll
    for (int o = 16; o > 0; o >>= 1) ss += __shfl_down_sync(0xffffffffu, ss, o);
    if ((tid & 31) == 0) red[tid >> 5] = ss;
    __syncthreads();
    if (tid < 32) {
        float v = (tid < 8) ? red[tid] : 0.f;
#pragma unroll
        for (int o = 4; o > 0; o >>= 1) v += __shfl_down_sync(0xffffffffu, v, o);
        if (tid == 0) red[0] = v;
    }
    __syncthreads();
    const float inv = rsqrtf(red[0] / (float)D_INNER + 1e-5f);
#pragma unroll
    for (int i = 0; i < 8; i++) {
        const int c = tid + i * 256;
        g_yg[(size_t)row * D_INNER + c] = rnd_tf32(vals[i] * inv * normw[c]);
    }
}

// ---------------- rms over D: xn = rms(x1) * rms_w   (tf32-rounded out) ----------------
__global__ __launch_bounds__(256) void rms_kernel(const float* __restrict__ w)
{
    const int row = blockIdx.x;
    const int tid = threadIdx.x;
    const float* xr = g_x1 + (size_t)row * D_SZ;

    float vals[4];
    float ss = 0.f;
#pragma unroll
    for (int i = 0; i < 4; i++) {
        const int c = tid + i * 256;
        vals[i] = xr[c];
        ss = fmaf(vals[i], vals[i], ss);
    }
    __shared__ float red[32];
#pragma unroll
    for (int o = 16; o > 0; o >>= 1) ss += __shfl_down_sync(0xffffffffu, ss, o);
    if ((tid & 31) == 0) red[tid >> 5] = ss;
    __syncthreads();
    if (tid < 32) {
        float v = (tid < 8) ? red[tid] : 0.f;
#pragma unroll
        for (int o = 4; o > 0; o >>= 1) v += __shfl_down_sync(0xffffffffu, v, o);
        if (tid == 0) red[0] = v;
    }
    __syncthreads();
    const float inv = rsqrtf(red[0] / (float)D_SZ + 1e-5f);
#pragma unroll
    for (int i = 0; i < 4; i++) {
        const int c = tid + i * 256;
        g_xn[(size_t)row * D_SZ + c] = rnd_tf32(vals[i] * inv * w[c]);
    }
}

// ---------------- GLU: m_in = a * silu(g)   (tf32-rounded out) ----------------
__global__ void glu_kernel()
{
    const int idx = blockIdx.x * blockDim.x + threadIdx.x;
    if (idx >= ROWS * H_MLP2) return;
    const int j = idx % H_MLP2;
    const int r = idx / H_MLP2;
    const float a = g_h1[(size_t)r * H_MLP + j];
    const float g = g_h1[(size_t)r * H_MLP + H_MLP2 + j];
    g_min[idx] = rnd_tf32(a * silu_f(g));
}

// ---------------- launch ----------------
extern "C" void kernel_launch(void* const* d_in, const int* in_sizes, int n_in,
                              void* d_out, int out_size)
{
    const float* x          = (const float*)d_in[0];
    const float* in_proj_w  = (const float*)d_in[1];
    const float* conv_w     = (const float*)d_in[2];
    const float* conv_b     = (const float*)d_in[3];
    const float* dt_bias    = (const float*)d_in[4];
    const float* A_log      = (const float*)d_in[5];
    const float* Dp         = (const float*)d_in[6];
    const float* ssm_norm_w = (const float*)d_in[7];
    const float* out_proj_w = (const float*)d_in[8];
    const float* rms_w      = (const float*)d_in[9];
    const float* fc1_w      = (const float*)d_in[10];
    const float* fc2_w      = (const float*)d_in[11];
    float* out = (float*)d_out;

    float *p_zx, *p_yg, *p_x1, *p_xn, *p_h1, *p_min;
    float *p_xc, *p_wip, *p_wop, *p_wf1, *p_wf2;
    cudaGetSymbolAddress((void**)&p_zx,  g_zxbcdt);
    cudaGetSymbolAddress((void**)&p_yg,  g_yg);
    cudaGetSymbolAddress((void**)&p_x1,  g_x1);
    cudaGetSymbolAddress((void**)&p_xn,  g_xn);
    cudaGetSymbolAddress((void**)&p_h1,  g_h1);
    cudaGetSymbolAddress((void**)&p_min, g_min);
    cudaGetSymbolAddress((void**)&p_xc,  g_xc);
    cudaGetSymbolAddress((void**)&p_wip, g_wip);
    cudaGetSymbolAddress((void**)&p_wop, g_wop);
    cudaGetSymbolAddress((void**)&p_wf1, g_wf1);
    cudaGetSymbolAddress((void**)&p_wf2, g_wf2);

    const int gemm_smem = SMEM_WORDS * 4;   // 81920 B
    cudaFuncSetAttribute(tf32_gemm_kernel,
                         cudaFuncAttributeMaxDynamicSharedMemorySize, gemm_smem);

    // 0) tf32-round GEMM operands coming straight from inputs
    cvt_kernel<<<(ROWS * D_SZ / 4 + 255) / 256, 256>>>(x, p_xc, ROWS * D_SZ / 4);
    cvt_kernel<<<(D_IN_PROJ * D_SZ / 4 + 255) / 256, 256>>>(in_proj_w, p_wip, D_IN_PROJ * D_SZ / 4);
    cvt_kernel<<<(D_SZ * D_INNER / 4 + 255) / 256, 256>>>(out_proj_w, p_wop, D_SZ * D_INNER / 4);
    cvt_kernel<<<(H_MLP * D_SZ / 4 + 255) / 256, 256>>>(fc1_w, p_wf1, H_MLP * D_SZ / 4);
    cvt_kernel<<<(D_SZ * H_MLP2 / 4 + 255) / 256, 256>>>(fc2_w, p_wf2, D_SZ * H_MLP2 / 4);

    // 1) in_proj: zxbcdt[2048,4256] = xc @ wip^T
    {
        dim3 grid((D_IN_PROJ + 127) / 128, ROWS / 128);
        tf32_gemm_kernel<<<grid, 256, gemm_smem>>>(p_xc, p_wip, nullptr, p_zx, ROWS, D_IN_PROJ, D_SZ);
    }
    // 2) dt/dA
    dt_kernel<<<(ROWS * NHEADS + 255) / 256, 256>>>(dt_bias, A_log);
    // 3) conv + silu
    conv_silu_kernel<<<(ROWS * CONV_DIM + 255) / 256, 256>>>(conv_w, conv_b);
    // 4) scan
    scan_kernel<<<B_SZ * NHEADS * 4, 1024>>>();
    // 5) gate + rms(ssm_norm)
    gate_rms_kernel<<<ROWS, 256>>>(Dp, ssm_norm_w);
    // 6) out_proj + residual: x1 = x + yg @ wop^T
    {
        dim3 grid(D_SZ / 128, ROWS / 128);
        tf32_gemm_kernel<<<grid, 256, gemm_smem>>>(p_yg, p_wop, x, p_x1, ROWS, D_SZ, D_INNER);
    }
    // 7) rms
    rms_kernel<<<ROWS, 256>>>(rms_w);
    // 8) fc1: h1 = xn @ wf1^T
    {
        dim3 grid(H_MLP / 128, ROWS / 128);
        tf32_gemm_kernel<<<grid, 256, gemm_smem>>>(p_xn, p_wf1, nullptr, p_h1, ROWS, H_MLP, D_SZ);
    }
    // 9) GLU
    glu_kernel<<<(ROWS * H_MLP2 + 255) / 256, 256>>>();
    // 10) fc2 + residual: out = x1 + min @ wf2^T
    {
        dim3 grid(D_SZ / 128, ROWS / 128);
        tf32_gemm_kernel<<<grid, 256, gemm_smem>>>(p_min, p_wf2, p_x1, out, ROWS, D_SZ, H_MLP2);
    }
}

// round 5
// speedup vs baseline: 2.5959x; 1.2456x over previous
#include <cuda_runtime.h>
#include <cuda_fp16.h>
#include <cstdint>
#include <cstdio>

// ---------------- problem constants ----------------
#define B_SZ 2
#define S_SZ 1024
#define D_SZ 1024
#define D_INNER 2048
#define HEADDIM 64
#define NHEADS 32
#define D_STATE 64
#define D_CONV 4
#define CONV_DIM (D_INNER + 2 * D_STATE)                 // 2176
#define D_IN_PROJ (2 * D_INNER + 2 * D_STATE + NHEADS)   // 4256
#define H_MLP 8192
#define H_MLP2 4096
#define ROWS (B_SZ * S_SZ)                               // 2048

// ---------------- scratch (device globals; no allocation allowed) ----------------
__device__ float g_zxbcdt[ROWS * D_IN_PROJ];
__device__ float g_xbc[ROWS * CONV_DIM];
__device__ float g_dt[ROWS * NHEADS];
__device__ float g_dA[ROWS * NHEADS];
__device__ float g_y[ROWS * D_INNER];
__device__ float g_x1[ROWS * D_SZ];
__device__ float g_h1[ROWS * H_MLP];
// fp16 GEMM operands
__device__ __half g_xh [ROWS * D_SZ];
__device__ __half g_wip[D_IN_PROJ * D_SZ];
__device__ __half g_wop[D_SZ * D_INNER];
__device__ __half g_wf1[H_MLP * D_SZ];
__device__ __half g_wf2[D_SZ * H_MLP2];
__device__ __half g_yg [ROWS * D_INNER];
__device__ __half g_xn [ROWS * D_SZ];
__device__ __half g_min[ROWS * H_MLP2];

__device__ __forceinline__ float silu_f(float v) {
    return v / (1.f + __expf(-v));
}
__device__ __forceinline__ uint32_t smem_u32(const void* p) {
    uint32_t a;
    asm("{ .reg .u64 t; cvta.to.shared.u64 t, %1; cvt.u32.u64 %0, t; }" : "=r"(a) : "l"(p));
    return a;
}
__device__ __forceinline__ void cp_async16(uint32_t dst, const void* src) {
    asm volatile("cp.async.cg.shared.global [%0], [%1], 16;" :: "r"(dst), "l"(src));
}
#define CP_COMMIT() asm volatile("cp.async.commit_group;" ::: "memory")
#define CP_WAIT(n)  asm volatile("cp.async.wait_group %0;" :: "n"(n) : "memory")

// ---------------- pipelined fp16 mma.sync GEMM ----------------
// C[M,N] = A[M,K] @ W[N,K]^T (+ addend fp32). A, W are fp16 (rn-rounded).
// 128x128 CTA tile, BK=32 halves per stage, 4-stage cp.async pipeline,
// 8 warps (2m x 4n), warp tile 64x32, mma.m16n8k16.f32.f16.f16.f32.
// M % 128 == 0, K % 32 == 0, partial last N-tile handled.
#define HPITCHW 20                   // words per smem row (64B data + 16B pad)
#define ASTGW (128 * HPITCHW)        // words per operand per stage = 2560
#define STGW  (2 * ASTGW)            // words per stage = 5120 (20480 B)
#define NSTG  4
#define GEMM_SMEM_BYTES (NSTG * STGW * 4)   // 81920

__global__ __launch_bounds__(256, 2) void hgemm_kernel(
    const __half* __restrict__ A, const __half* __restrict__ W,
    const float* __restrict__ addend, float* __restrict__ C,
    int M, int N, int K)
{
    extern __shared__ uint32_t sm[];
    const uint32_t sb = smem_u32(sm);

    const int tid = threadIdx.x;
    const int bm = blockIdx.y * 128;
    const int bn = blockIdx.x * 128;

    const int warp = tid >> 5;
    const int lane = tid & 31;
    const int g  = lane >> 2;
    const int t4 = lane & 3;
    const int warp_m = (warp >> 2) * 64;
    const int warp_n = (warp & 3) * 32;

    // load mapping: thread handles rows {lr, lr+64}, 16B chunk q (8 halves)
    const int lr = tid >> 2;            // 0..63
    const int q  = tid & 3;             // 0..3

    const __half* Ap0 = A + (size_t)(bm + lr) * K + q * 8;
    const __half* Ap1 = A + (size_t)(bm + 64 + lr) * K + q * 8;
    int wr0 = bn + lr;      if (wr0 > N - 1) wr0 = N - 1;
    int wr1 = bn + 64 + lr; if (wr1 > N - 1) wr1 = N - 1;
    const __half* Wp0 = W + (size_t)wr0 * K + q * 8;
    const __half* Wp1 = W + (size_t)wr1 * K + q * 8;

    const uint32_t d0 = (uint32_t)lr * 80 + q * 16;   // bytes within operand stage
    const uint32_t d1 = d0 + 64 * 80;
    const int T = K / 32;

    float acc[4][4][4];
#pragma unroll
    for (int i = 0; i < 4; i++)
#pragma unroll
        for (int j = 0; j < 4; j++)
#pragma unroll
            for (int r = 0; r < 4; r++) acc[i][j][r] = 0.f;

    auto load_stage = [&](int j) {
        if (j < T) {
            const uint32_t base = sb + (j & (NSTG - 1)) * (STGW * 4);
            const int ko = j * 32;
            cp_async16(base + d0, Ap0 + ko);
            cp_async16(base + d1, Ap1 + ko);
            cp_async16(base + ASTGW * 4 + d0, Wp0 + ko);
            cp_async16(base + ASTGW * 4 + d1, Wp1 + ko);
        }
        CP_COMMIT();
    };

    load_stage(0);
    load_stage(1);
    load_stage(2);

    for (int kt = 0; kt < T; kt++) {
        CP_WAIT(2);
        __syncthreads();
        load_stage(kt + 3);

        const uint32_t* As = sm + (kt & (NSTG - 1)) * STGW;
        const uint32_t* Bs = As + ASTGW;
#pragma unroll
        for (int kw = 0; kw < 16; kw += 8) {     // two K=16 chunks (word offsets)
            uint32_t af[4][4];
            uint32_t bf[4][2];
#pragma unroll
            for (int mt = 0; mt < 4; mt++) {
                const int r0 = warp_m + mt * 16 + g;
                af[mt][0] = As[r0 * HPITCHW + kw + t4];
                af[mt][1] = As[(r0 + 8) * HPITCHW + kw + t4];
                af[mt][2] = As[r0 * HPITCHW + kw + t4 + 4];
                af[mt][3] = As[(r0 + 8) * HPITCHW + kw + t4 + 4];
            }
#pragma unroll
            for (int nt = 0; nt < 4; nt++) {
                const int c0 = warp_n + nt * 8 + g;
                bf[nt][0] = Bs[c0 * HPITCHW + kw + t4];
                bf[nt][1] = Bs[c0 * HPITCHW + kw + t4 + 4];
            }
#pragma unroll
            for (int mt = 0; mt < 4; mt++)
#pragma unroll
                for (int nt = 0; nt < 4; nt++) {
                    asm volatile(
                        "mma.sync.aligned.m16n8k16.row.col.f32.f16.f16.f32 "
                        "{%0,%1,%2,%3}, {%4,%5,%6,%7}, {%8,%9}, {%0,%1,%2,%3};"
                        : "+f"(acc[mt][nt][0]), "+f"(acc[mt][nt][1]),
                          "+f"(acc[mt][nt][2]), "+f"(acc[mt][nt][3])
                        : "r"(af[mt][0]), "r"(af[mt][1]), "r"(af[mt][2]), "r"(af[mt][3]),
                          "r"(bf[nt][0]), "r"(bf[nt][1]));
                }
        }
    }

    // epilogue
#pragma unroll
    for (int mt = 0; mt < 4; mt++) {
        const int row0 = bm + warp_m + mt * 16 + g;
#pragma unroll
        for (int nt = 0; nt < 4; nt++) {
            const int col = bn + warp_n + nt * 8 + 2 * t4;
            if (col < N) {
                float2 v0 = make_float2(acc[mt][nt][0], acc[mt][nt][1]);
                float2 v1 = make_float2(acc[mt][nt][2], acc[mt][nt][3]);
                if (addend) {
                    const float2 a0 = *reinterpret_cast<const float2*>(&addend[(size_t)row0 * N + col]);
                    const float2 a1 = *reinterpret_cast<const float2*>(&addend[(size_t)(row0 + 8) * N + col]);
                    v0.x += a0.x; v0.y += a0.y;
                    v1.x += a1.x; v1.y += a1.y;
                }
                *reinterpret_cast<float2*>(&C[(size_t)row0 * N + col]) = v0;
                *reinterpret_cast<float2*>(&C[(size_t)(row0 + 8) * N + col]) = v1;
            }
        }
    }
}

// ---------------- fp32 -> fp16 conversion ----------------
__global__ void cvt_h_kernel(const float* __restrict__ in, __half* __restrict__ out, int n4)
{
    const int i = blockIdx.x * blockDim.x + threadIdx.x;
    if (i >= n4) return;
    float4 v = reinterpret_cast<const float4*>(in)[i];
    __half2 h0 = __floats2half2_rn(v.x, v.y);
    __half2 h1 = __floats2half2_rn(v.z, v.w);
    *reinterpret_cast<uint2*>(out + (size_t)i * 4) =
        make_uint2(*reinterpret_cast<uint32_t*>(&h0), *reinterpret_cast<uint32_t*>(&h1));
}

// ---------------- causal depthwise conv (k=4) + bias + silu ----------------
__global__ void conv_silu_kernel(const float* __restrict__ conv_w,
                                 const float* __restrict__ conv_b)
{
    const int idx = blockIdx.x * blockDim.x + threadIdx.x;
    if (idx >= ROWS * CONV_DIM) return;
    const int c = idx % CONV_DIM;
    const int bs = idx / CONV_DIM;
    const int s = bs % S_SZ;
    const int b = bs / S_SZ;

    float acc = conv_b[c];
#pragma unroll
    for (int k = 0; k < D_CONV; k++) {
        const int ss = s - (D_CONV - 1) + k;
        if (ss >= 0)
            acc = fmaf(g_zxbcdt[(size_t)(b * S_SZ + ss) * D_IN_PROJ + D_INNER + c],
                       conv_w[c * D_CONV + k], acc);
    }
    g_xbc[idx] = silu_f(acc);
}

// ---------------- dt/dA ----------------
__global__ void dt_kernel(const float* __restrict__ dt_bias,
                          const float* __restrict__ A_log)
{
    const int idx = blockIdx.x * blockDim.x + threadIdx.x;
    if (idx >= ROWS * NHEADS) return;
    const int h = idx % NHEADS;
    const int r = idx / NHEADS;
    float x = g_zxbcdt[(size_t)r * D_IN_PROJ + (D_IN_PROJ - NHEADS) + h] + dt_bias[h];
    float dt = (x > 20.f) ? x : log1pf(expf(x));
    g_dt[idx] = dt;
    g_dA[idx] = expf(-expf(A_log[h]) * dt);
}

// ---------------- sequential SSM scan ----------------
__global__ __launch_bounds__(1024) void scan_kernel()
{
    const int pc = blockIdx.x & 3;
    const int h  = (blockIdx.x >> 2) & (NHEADS - 1);
    const int b  = blockIdx.x >> 7;

    const int tid  = threadIdx.x;
    const int n    = tid & 63;
    const int pl   = tid >> 6;
    const int lane = tid & 31;
    const int half = (n >= 32) ? 1 : 0;

    __shared__ float sB[D_STATE], sC[D_STATE], sx[16];
    __shared__ float sy[16][2];
    __shared__ float sdt, sdA;

    float hst = 0.f;

    for (int s = 0; s < S_SZ; s++) {
        const float* row = g_xbc + (size_t)(b * S_SZ + s) * CONV_DIM;
        if (tid < 64)        sB[tid]        = row[D_INNER + tid];
        else if (tid < 128)  sC[tid - 64]   = row[D_INNER + D_STATE + (tid - 64)];
        else if (tid < 144)  sx[tid - 128]  = row[h * HEADDIM + pc * 16 + (tid - 128)];
        else if (tid == 144) {
            const int i = (b * S_SZ + s) * NHEADS + h;
            sdt = g_dt[i];
            sdA = g_dA[i];
        }
        __syncthreads();

        hst = fmaf(hst, sdA, (sdt * sx[pl]) * sB[n]);
        float part = hst * sC[n];
        part += __shfl_down_sync(0xffffffffu, part, 16);
        part += __shfl_down_sync(0xffffffffu, part, 8);
        part += __shfl_down_sync(0xffffffffu, part, 4);
        part += __shfl_down_sync(0xffffffffu, part, 2);
        part += __shfl_down_sync(0xffffffffu, part, 1);
        if (lane == 0) sy[pl][half] = part;
        __syncthreads();

        if (tid < 16)
            g_y[((size_t)(b * S_SZ + s) * NHEADS + h) * HEADDIM + pc * 16 + tid] =
                sy[tid][0] + sy[tid][1];
    }
}

// ---------------- gate: yg = rms((y + D*xs) * silu(z)) * w  -> fp16 ----------------
__global__ __launch_bounds__(256) void gate_rms_kernel(const float* __restrict__ Dp,
                                                       const float* __restrict__ normw)
{
    const int row = blockIdx.x;
    const int tid = threadIdx.x;

    const float* yr = g_y      + (size_t)row * D_INNER;
    const float* xb = g_xbc    + (size_t)row * CONV_DIM;
    const float* zr = g_zxbcdt + (size_t)row * D_IN_PROJ;

    float vals[8];
    float ss = 0.f;
#pragma unroll
    for (int i = 0; i < 8; i++) {
        const int c = tid + i * 256;
        float v = fmaf(Dp[c >> 6], xb[c], yr[c]);
        v *= silu_f(zr[c]);
        vals[i] = v;
        ss = fmaf(v, v, ss);
    }
    __shared__ float red[32];
#pragma unroll
    for (int o = 16; o > 0; o >>= 1) ss += __shfl_down_sync(0xffffffffu, ss, o);
    if ((tid & 31) == 0) red[tid >> 5] = ss;
    __syncthreads();
    if (tid < 32) {
        float v = (tid < 8) ? red[tid] : 0.f;
#pragma unroll
        for (int o = 4; o > 0; o >>= 1) v += __shfl_down_sync(0xffffffffu, v, o);
        if (tid == 0) red[0] = v;
    }
    __syncthreads();
    const float inv = rsqrtf(red[0] / (float)D_INNER + 1e-5f);
#pragma unroll
    for (int i = 0; i < 8; i++) {
        const int c = tid + i * 256;
        g_yg[(size_t)row * D_INNER + c] = __float2half_rn(vals[i] * inv * normw[c]);
    }
}

// ---------------- rms over D: xn = rms(x1) * rms_w  -> fp16 ----------------
__global__ __launch_bounds__(256) void rms_kernel(const float* __restrict__ w)
{
    const int row = blockIdx.x;
    const int tid = threadIdx.x;
    const float* xr = g_x1 + (size_t)row * D_SZ;

    float vals[4];
    float ss = 0.f;
#pragma unroll
    for (int i = 0; i < 4; i++) {
        const int c = tid + i * 256;
        vals[i] = xr[c];
        ss = fmaf(vals[i], vals[i], ss);
    }
    __shared__ float red[32];
#pragma unroll
    for (int o = 16; o > 0; o >>= 1) ss += __shfl_down_sync(0xffffffffu, ss, o);
    if ((tid & 31) == 0) red[tid >> 5] = ss;
    __syncthreads();
    if (tid < 32) {
        float v = (tid < 8) ? red[tid] : 0.f;
#pragma unroll
        for (int o = 4; o > 0; o >>= 1) v += __shfl_down_sync(0xffffffffu, v, o);
        if (tid == 0) red[0] = v;
    }
    __syncthreads();
    const float inv = rsqrtf(red[0] / (float)D_SZ + 1e-5f);
#pragma unroll
    for (int i = 0; i < 4; i++) {
        const int c = tid + i * 256;
        g_xn[(size_t)row * D_SZ + c] = __float2half_rn(vals[i] * inv * w[c]);
    }
}

// ---------------- GLU: m_in = a * silu(g)  -> fp16 ----------------
__global__ void glu_kernel()
{
    const int idx = blockIdx.x * blockDim.x + threadIdx.x;
    if (idx >= ROWS * H_MLP2) return;
    const int j = idx % H_MLP2;
    const int r = idx / H_MLP2;
    const float a = g_h1[(size_t)r * H_MLP + j];
    const float g = g_h1[(size_t)r * H_MLP + H_MLP2 + j];
    g_min[idx] = __float2half_rn(a * silu_f(g));
}

// ---------------- launch ----------------
extern "C" void kernel_launch(void* const* d_in, const int* in_sizes, int n_in,
                              void* d_out, int out_size)
{
    const float* x          = (const float*)d_in[0];
    const float* in_proj_w  = (const float*)d_in[1];
    const float* conv_w     = (const float*)d_in[2];
    const float* conv_b     = (const float*)d_in[3];
    const float* dt_bias    = (const float*)d_in[4];
    const float* A_log      = (const float*)d_in[5];
    const float* Dp         = (const float*)d_in[6];
    const float* ssm_norm_w = (const float*)d_in[7];
    const float* out_proj_w = (const float*)d_in[8];
    const float* rms_w      = (const float*)d_in[9];
    const float* fc1_w      = (const float*)d_in[10];
    const float* fc2_w      = (const float*)d_in[11];
    float* out = (float*)d_out;

    float *p_zx, *p_x1, *p_h1;
    __half *p_xh, *p_wip, *p_wop, *p_wf1, *p_wf2, *p_yg, *p_xn, *p_min;
    cudaGetSymbolAddress((void**)&p_zx,  g_zxbcdt);
    cudaGetSymbolAddress((void**)&p_x1,  g_x1);
    cudaGetSymbolAddress((void**)&p_h1,  g_h1);
    cudaGetSymbolAddress((void**)&p_xh,  g_xh);
    cudaGetSymbolAddress((void**)&p_wip, g_wip);
    cudaGetSymbolAddress((void**)&p_wop, g_wop);
    cudaGetSymbolAddress((void**)&p_wf1, g_wf1);
    cudaGetSymbolAddress((void**)&p_wf2, g_wf2);
    cudaGetSymbolAddress((void**)&p_yg,  g_yg);
    cudaGetSymbolAddress((void**)&p_xn,  g_xn);
    cudaGetSymbolAddress((void**)&p_min, g_min);

    cudaFuncSetAttribute(hgemm_kernel,
                         cudaFuncAttributeMaxDynamicSharedMemorySize, GEMM_SMEM_BYTES);

    // 0) fp16-round GEMM operands coming straight from inputs
    cvt_h_kernel<<<(ROWS * D_SZ / 4 + 255) / 256, 256>>>(x, p_xh, ROWS * D_SZ / 4);
    cvt_h_kernel<<<(D_IN_PROJ * D_SZ / 4 + 255) / 256, 256>>>(in_proj_w, p_wip, D_IN_PROJ * D_SZ / 4);
    cvt_h_kernel<<<(D_SZ * D_INNER / 4 + 255) / 256, 256>>>(out_proj_w, p_wop, D_SZ * D_INNER / 4);
    cvt_h_kernel<<<(H_MLP * D_SZ / 4 + 255) / 256, 256>>>(fc1_w, p_wf1, H_MLP * D_SZ / 4);
    cvt_h_kernel<<<(D_SZ * H_MLP2 / 4 + 255) / 256, 256>>>(fc2_w, p_wf2, D_SZ * H_MLP2 / 4);

    // 1) in_proj: zxbcdt[2048,4256] = xh @ wip^T
    {
        dim3 grid((D_IN_PROJ + 127) / 128, ROWS / 128);
        hgemm_kernel<<<grid, 256, GEMM_SMEM_BYTES>>>(p_xh, p_wip, nullptr, p_zx, ROWS, D_IN_PROJ, D_SZ);
    }
    // 2) dt/dA
    dt_kernel<<<(ROWS * NHEADS + 255) / 256, 256>>>(dt_bias, A_log);
    // 3) conv + silu
    conv_silu_kernel<<<(ROWS * CONV_DIM + 255) / 256, 256>>>(conv_w, conv_b);
    // 4) scan
    scan_kernel<<<B_SZ * NHEADS * 4, 1024>>>();
    // 5) gate + rms(ssm_norm)
    gate_rms_kernel<<<ROWS, 256>>>(Dp, ssm_norm_w);
    // 6) out_proj + residual: x1 = x + yg @ wop^T
    {
        dim3 grid(D_SZ / 128, ROWS / 128);
        hgemm_kernel<<<grid, 256, GEMM_SMEM_BYTES>>>(p_yg, p_wop, x, p_x1, ROWS, D_SZ, D_INNER);
    }
    // 7) rms
    rms_kernel<<<ROWS, 256>>>(rms_w);
    // 8) fc1: h1 = xn @ wf1^T
    {
        dim3 grid(H_MLP / 128, ROWS / 128);
        hgemm_kernel<<<grid, 256, GEMM_SMEM_BYTES>>>(p_xn, p_wf1, nullptr, p_h1, ROWS, H_MLP, D_SZ);
    }
    // 9) GLU
    glu_kernel<<<(ROWS * H_MLP2 + 255) / 256, 256>>>();
    // 10) fc2 + residual: out = x1 + min @ wf2^T
    {
        dim3 grid(D_SZ / 128, ROWS / 128);
        hgemm_kernel<<<grid, 256, GEMM_SMEM_BYTES>>>(p_min, p_wf2, p_x1, out, ROWS, D_SZ, H_MLP2);
    }
}

// round 6
// speedup vs baseline: 2.6273x; 1.0121x over previous
#include <cuda_runtime.h>
#include <cuda_fp16.h>
#include <cstdint>
#include <cstdio>

// ---------------- problem constants ----------------
#define B_SZ 2
#define S_SZ 1024
#define D_SZ 1024
#define D_INNER 2048
#define HEADDIM 64
#define NHEADS 32
#define D_STATE 64
#define D_CONV 4
#define CONV_DIM (D_INNER + 2 * D_STATE)                 // 2176
#define D_IN_PROJ (2 * D_INNER + 2 * D_STATE + NHEADS)   // 4256
#define H_MLP 8192
#define H_MLP2 4096
#define ROWS (B_SZ * S_SZ)                               // 2048

// ---------------- scratch (device globals; no allocation allowed) ----------------
__device__ float g_zxbcdt[ROWS * D_IN_PROJ];
__device__ float g_xbc[ROWS * CONV_DIM];
__device__ float g_dt[ROWS * NHEADS];
__device__ float g_dA[ROWS * NHEADS];
__device__ float g_y[ROWS * D_INNER];
__device__ float g_x1[ROWS * D_SZ];
__device__ float g_h1[ROWS * H_MLP];
__device__ float g_part[4 * ROWS * D_SZ];                // split-K partials
// fp16 GEMM operands
__device__ __half g_xh [ROWS * D_SZ];
__device__ __half g_wip[D_IN_PROJ * D_SZ];
__device__ __half g_wop[D_SZ * D_INNER];
__device__ __half g_wf1[H_MLP * D_SZ];
__device__ __half g_wf2[D_SZ * H_MLP2];
__device__ __half g_yg [ROWS * D_INNER];
__device__ __half g_xn [ROWS * D_SZ];
__device__ __half g_min[ROWS * H_MLP2];

__device__ __forceinline__ float silu_f(float v) {
    return v / (1.f + __expf(-v));
}
__device__ __forceinline__ uint32_t smem_u32(const void* p) {
    uint32_t a;
    asm("{ .reg .u64 t; cvta.to.shared.u64 t, %1; cvt.u32.u64 %0, t; }" : "=r"(a) : "l"(p));
    return a;
}
__device__ __forceinline__ void cp_async16(uint32_t dst, const void* src) {
    asm volatile("cp.async.cg.shared.global [%0], [%1], 16;" :: "r"(dst), "l"(src));
}
#define CP_COMMIT() asm volatile("cp.async.commit_group;" ::: "memory")
#define CP_WAIT(n)  asm volatile("cp.async.wait_group %0;" :: "n"(n) : "memory")

// ---------------- pipelined fp16 mma.sync GEMM with optional split-K ----------------
// Computes C_part = A[M, kbeg:kbeg+kchunk] @ W[N, same]^T per blockIdx.z.
// If gridDim.z == 1: writes C (+addend). Else: writes raw partial to
// Cpart + z*M*N (addend applied later by reduce kernel).
// 128x128 CTA tile, BK=32 halves, 4-stage cp.async pipeline, 8 warps,
// warp tile 64x32, mma.m16n8k16.f32.f16.f16.f32.
#define HPITCHW 20
#define ASTGW (128 * HPITCHW)
#define STGW  (2 * ASTGW)
#define NSTG  4
#define GEMM_SMEM_BYTES (NSTG * STGW * 4)   // 81920

__global__ __launch_bounds__(256, 2) void hgemm_kernel(
    const __half* __restrict__ A, const __half* __restrict__ W,
    const float* __restrict__ addend, float* __restrict__ C,
    int M, int N, int K, int kchunk)
{
    extern __shared__ uint32_t sm[];
    const uint32_t sb = smem_u32(sm);

    const int tid = threadIdx.x;
    const int bm = blockIdx.y * 128;
    const int bn = blockIdx.x * 128;
    const int kbeg = blockIdx.z * kchunk;
    const bool partial = (gridDim.z > 1);

    const int warp = tid >> 5;
    const int lane = tid & 31;
    const int g  = lane >> 2;
    const int t4 = lane & 3;
    const int warp_m = (warp >> 2) * 64;
    const int warp_n = (warp & 3) * 32;

    const int lr = tid >> 2;
    const int q  = tid & 3;

    const __half* Ap0 = A + (size_t)(bm + lr) * K + kbeg + q * 8;
    const __half* Ap1 = A + (size_t)(bm + 64 + lr) * K + kbeg + q * 8;
    int wr0 = bn + lr;      if (wr0 > N - 1) wr0 = N - 1;
    int wr1 = bn + 64 + lr; if (wr1 > N - 1) wr1 = N - 1;
    const __half* Wp0 = W + (size_t)wr0 * K + kbeg + q * 8;
    const __half* Wp1 = W + (size_t)wr1 * K + kbeg + q * 8;

    const uint32_t d0 = (uint32_t)lr * 80 + q * 16;
    const uint32_t d1 = d0 + 64 * 80;
    const int T = kchunk / 32;

    float acc[4][4][4];
#pragma unroll
    for (int i = 0; i < 4; i++)
#pragma unroll
        for (int j = 0; j < 4; j++)
#pragma unroll
            for (int r = 0; r < 4; r++) acc[i][j][r] = 0.f;

    auto load_stage = [&](int j) {
        if (j < T) {
            const uint32_t base = sb + (j & (NSTG - 1)) * (STGW * 4);
            const int ko = j * 32;
            cp_async16(base + d0, Ap0 + ko);
            cp_async16(base + d1, Ap1 + ko);
            cp_async16(base + ASTGW * 4 + d0, Wp0 + ko);
            cp_async16(base + ASTGW * 4 + d1, Wp1 + ko);
        }
        CP_COMMIT();
    };

    load_stage(0);
    load_stage(1);
    load_stage(2);

    for (int kt = 0; kt < T; kt++) {
        CP_WAIT(2);
        __syncthreads();
        load_stage(kt + 3);

        const uint32_t* As = sm + (kt & (NSTG - 1)) * STGW;
        const uint32_t* Bs = As + ASTGW;
#pragma unroll
        for (int kw = 0; kw < 16; kw += 8) {
            uint32_t af[4][4];
            uint32_t bf[4][2];
#pragma unroll
            for (int mt = 0; mt < 4; mt++) {
                const int r0 = warp_m + mt * 16 + g;
                af[mt][0] = As[r0 * HPITCHW + kw + t4];
                af[mt][1] = As[(r0 + 8) * HPITCHW + kw + t4];
                af[mt][2] = As[r0 * HPITCHW + kw + t4 + 4];
                af[mt][3] = As[(r0 + 8) * HPITCHW + kw + t4 + 4];
            }
#pragma unroll
            for (int nt = 0; nt < 4; nt++) {
                const int c0 = warp_n + nt * 8 + g;
                bf[nt][0] = Bs[c0 * HPITCHW + kw + t4];
                bf[nt][1] = Bs[c0 * HPITCHW + kw + t4 + 4];
            }
#pragma unroll
            for (int mt = 0; mt < 4; mt++)
#pragma unroll
                for (int nt = 0; nt < 4; nt++) {
                    asm volatile(
                        "mma.sync.aligned.m16n8k16.row.col.f32.f16.f16.f32 "
                        "{%0,%1,%2,%3}, {%4,%5,%6,%7}, {%8,%9}, {%0,%1,%2,%3};"
                        : "+f"(acc[mt][nt][0]), "+f"(acc[mt][nt][1]),
                          "+f"(acc[mt][nt][2]), "+f"(acc[mt][nt][3])
                        : "r"(af[mt][0]), "r"(af[mt][1]), "r"(af[mt][2]), "r"(af[mt][3]),
                          "r"(bf[nt][0]), "r"(bf[nt][1]));
                }
        }
    }

    float* Co = partial ? (C + (size_t)blockIdx.z * M * N) : C;

#pragma unroll
    for (int mt = 0; mt < 4; mt++) {
        const int row0 = bm + warp_m + mt * 16 + g;
#pragma unroll
        for (int nt = 0; nt < 4; nt++) {
            const int col = bn + warp_n + nt * 8 + 2 * t4;
            if (col < N) {
                float2 v0 = make_float2(acc[mt][nt][0], acc[mt][nt][1]);
                float2 v1 = make_float2(acc[mt][nt][2], acc[mt][nt][3]);
                if (!partial && addend) {
                    const float2 a0 = *reinterpret_cast<const float2*>(&addend[(size_t)row0 * N + col]);
                    const float2 a1 = *reinterpret_cast<const float2*>(&addend[(size_t)(row0 + 8) * N + col]);
                    v0.x += a0.x; v0.y += a0.y;
                    v1.x += a1.x; v1.y += a1.y;
                }
                *reinterpret_cast<float2*>(&Co[(size_t)row0 * N + col]) = v0;
                *reinterpret_cast<float2*>(&Co[(size_t)(row0 + 8) * N + col]) = v1;
            }
        }
    }
}

// ---------------- split-K reduction: out = addend + sum_z part[z] ----------------
template <int NSPLIT>
__global__ void reduce_kernel(const float* __restrict__ part,
                              const float* __restrict__ addend,
                              float* __restrict__ out, int n4)
{
    const int i = blockIdx.x * blockDim.x + threadIdx.x;
    if (i >= n4) return;
    float4 v = reinterpret_cast<const float4*>(addend)[i];
#pragma unroll
    for (int z = 0; z < NSPLIT; z++) {
        const float4 p = reinterpret_cast<const float4*>(part + (size_t)z * ROWS * D_SZ)[i];
        v.x += p.x; v.y += p.y; v.z += p.z; v.w += p.w;
    }
    reinterpret_cast<float4*>(out)[i] = v;
}

// ---------------- fp32 -> fp16 conversion ----------------
__global__ void cvt_h_kernel(const float* __restrict__ in, __half* __restrict__ out, int n4)
{
    const int i = blockIdx.x * blockDim.x + threadIdx.x;
    if (i >= n4) return;
    float4 v = reinterpret_cast<const float4*>(in)[i];
    __half2 h0 = __floats2half2_rn(v.x, v.y);
    __half2 h1 = __floats2half2_rn(v.z, v.w);
    *reinterpret_cast<uint2*>(out + (size_t)i * 4) =
        make_uint2(*reinterpret_cast<uint32_t*>(&h0), *reinterpret_cast<uint32_t*>(&h1));
}

// ---------------- causal depthwise conv (k=4) + bias + silu ----------------
__global__ void conv_silu_kernel(const float* __restrict__ conv_w,
                                 const float* __restrict__ conv_b)
{
    const int idx = blockIdx.x * blockDim.x + threadIdx.x;
    if (idx >= ROWS * CONV_DIM) return;
    const int c = idx % CONV_DIM;
    const int bs = idx / CONV_DIM;
    const int s = bs % S_SZ;
    const int b = bs / S_SZ;

    float acc = conv_b[c];
#pragma unroll
    for (int k = 0; k < D_CONV; k++) {
        const int ss = s - (D_CONV - 1) + k;
        if (ss >= 0)
            acc = fmaf(g_zxbcdt[(size_t)(b * S_SZ + ss) * D_IN_PROJ + D_INNER + c],
                       conv_w[c * D_CONV + k], acc);
    }
    g_xbc[idx] = silu_f(acc);
}

// ---------------- dt/dA ----------------
__global__ void dt_kernel(const float* __restrict__ dt_bias,
                          const float* __restrict__ A_log)
{
    const int idx = blockIdx.x * blockDim.x + threadIdx.x;
    if (idx >= ROWS * NHEADS) return;
    const int h = idx % NHEADS;
    const int r = idx / NHEADS;
    float x = g_zxbcdt[(size_t)r * D_IN_PROJ + (D_IN_PROJ - NHEADS) + h] + dt_bias[h];
    float dt = (x > 20.f) ? x : log1pf(expf(x));
    g_dt[idx] = dt;
    g_dA[idx] = expf(-expf(A_log[h]) * dt);
}

// ---------------- sequential SSM scan ----------------
__global__ __launch_bounds__(1024) void scan_kernel()
{
    const int pc = blockIdx.x & 3;
    const int h  = (blockIdx.x >> 2) & (NHEADS - 1);
    const int b  = blockIdx.x >> 7;

    const int tid  = threadIdx.x;
    const int n    = tid & 63;
    const int pl   = tid >> 6;
    const int lane = tid & 31;
    const int half = (n >= 32) ? 1 : 0;

    __shared__ float sB[D_STATE], sC[D_STATE], sx[16];
    __shared__ float sy[16][2];
    __shared__ float sdt, sdA;

    float hst = 0.f;

    for (int s = 0; s < S_SZ; s++) {
        const float* row = g_xbc + (size_t)(b * S_SZ + s) * CONV_DIM;
        if (tid < 64)        sB[tid]        = row[D_INNER + tid];
        else if (tid < 128)  sC[tid - 64]   = row[D_INNER + D_STATE + (tid - 64)];
        else if (tid < 144)  sx[tid - 128]  = row[h * HEADDIM + pc * 16 + (tid - 128)];
        else if (tid == 144) {
            const int i = (b * S_SZ + s) * NHEADS + h;
            sdt = g_dt[i];
            sdA = g_dA[i];
        }
        __syncthreads();

        hst = fmaf(hst, sdA, (sdt * sx[pl]) * sB[n]);
        float part = hst * sC[n];
        part += __shfl_down_sync(0xffffffffu, part, 16);
        part += __shfl_down_sync(0xffffffffu, part, 8);
        part += __shfl_down_sync(0xffffffffu, part, 4);
        part += __shfl_down_sync(0xffffffffu, part, 2);
        part += __shfl_down_sync(0xffffffffu, part, 1);
        if (lane == 0) sy[pl][half] = part;
        __syncthreads();

        if (tid < 16)
            g_y[((size_t)(b * S_SZ + s) * NHEADS + h) * HEADDIM + pc * 16 + tid] =
                sy[tid][0] + sy[tid][1];
    }
}

// ---------------- gate: yg = rms((y + D*xs) * silu(z)) * w  -> fp16 ----------------
__global__ __launch_bounds__(256) void gate_rms_kernel(const float* __restrict__ Dp,
                                                       const float* __restrict__ normw)
{
    const int row = blockIdx.x;
    const int tid = threadIdx.x;

    const float* yr = g_y      + (size_t)row * D_INNER;
    const float* xb = g_xbc    + (size_t)row * CONV_DIM;
    const float* zr = g_zxbcdt + (size_t)row * D_IN_PROJ;

    float vals[8];
    float ss = 0.f;
#pragma unroll
    for (int i = 0; i < 8; i++) {
        const int c = tid + i * 256;
        float v = fmaf(Dp[c >> 6], xb[c], yr[c]);
        v *= silu_f(zr[c]);
        vals[i] = v;
        ss = fmaf(v, v, ss);
    }
    __shared__ float red[32];
#pragma unroll
    for (int o = 16; o > 0; o >>= 1) ss += __shfl_down_sync(0xffffffffu, ss, o);
    if ((tid & 31) == 0) red[tid >> 5] = ss;
    __syncthreads();
    if (tid < 32) {
        float v = (tid < 8) ? red[tid] : 0.f;
#pragma unroll
        for (int o = 4; o > 0; o >>= 1) v += __shfl_down_sync(0xffffffffu, v, o);
        if (tid == 0) red[0] = v;
    }
    __syncthreads();
    const float inv = rsqrtf(red[0] / (float)D_INNER + 1e-5f);
#pragma unroll
    for (int i = 0; i < 8; i++) {
        const int c = tid + i * 256;
        g_yg[(size_t)row * D_INNER + c] = __float2half_rn(vals[i] * inv * normw[c]);
    }
}

// ---------------- rms over D: xn = rms(x1) * rms_w  -> fp16 ----------------
__global__ __launch_bounds__(256) void rms_kernel(const float* __restrict__ w)
{
    const int row = blockIdx.x;
    const int tid = threadIdx.x;
    const float* xr = g_x1 + (size_t)row * D_SZ;

    float vals[4];
    float ss = 0.f;
#pragma unroll
    for (int i = 0; i < 4; i++) {
        const int c = tid + i * 256;
        vals[i] = xr[c];
        ss = fmaf(vals[i], vals[i], ss);
    }
    __shared__ float red[32];
#pragma unroll
    for (int o = 16; o > 0; o >>= 1) ss += __shfl_down_sync(0xffffffffu, ss, o);
    if ((tid & 31) == 0) red[tid >> 5] = ss;
    __syncthreads();
    if (tid < 32) {
        float v = (tid < 8) ? red[tid] : 0.f;
#pragma unroll
        for (int o = 4; o > 0; o >>= 1) v += __shfl_down_sync(0xffffffffu, v, o);
        if (tid == 0) red[0] = v;
    }
    __syncthreads();
    const float inv = rsqrtf(red[0] / (float)D_SZ + 1e-5f);
#pragma unroll
    for (int i = 0; i < 4; i++) {
        const int c = tid + i * 256;
        g_xn[(size_t)row * D_SZ + c] = __float2half_rn(vals[i] * inv * w[c]);
    }
}

// ---------------- GLU: m_in = a * silu(g)  -> fp16 ----------------
__global__ void glu_kernel()
{
    const int idx = blockIdx.x * blockDim.x + threadIdx.x;
    if (idx >= ROWS * H_MLP2) return;
    const int j = idx % H_MLP2;
    const int r = idx / H_MLP2;
    const float a = g_h1[(size_t)r * H_MLP + j];
    const float g = g_h1[(size_t)r * H_MLP + H_MLP2 + j];
    g_min[idx] = __float2half_rn(a * silu_f(g));
}

// ---------------- launch ----------------
extern "C" void kernel_launch(void* const* d_in, const int* in_sizes, int n_in,
                              void* d_out, int out_size)
{
    const float* x          = (const float*)d_in[0];
    const float* in_proj_w  = (const float*)d_in[1];
    const float* conv_w     = (const float*)d_in[2];
    const float* conv_b     = (const float*)d_in[3];
    const float* dt_bias    = (const float*)d_in[4];
    const float* A_log      = (const float*)d_in[5];
    const float* Dp         = (const float*)d_in[6];
    const float* ssm_norm_w = (const float*)d_in[7];
    const float* out_proj_w = (const float*)d_in[8];
    const float* rms_w      = (const float*)d_in[9];
    const float* fc1_w      = (const float*)d_in[10];
    const float* fc2_w      = (const float*)d_in[11];
    float* out = (float*)d_out;

    float *p_zx, *p_x1, *p_h1, *p_part;
    __half *p_xh, *p_wip, *p_wop, *p_wf1, *p_wf2, *p_yg, *p_xn, *p_min;
    cudaGetSymbolAddress((void**)&p_zx,  g_zxbcdt);
    cudaGetSymbolAddress((void**)&p_x1,  g_x1);
    cudaGetSymbolAddress((void**)&p_h1,  g_h1);
    cudaGetSymbolAddress((void**)&p_part, g_part);
    cudaGetSymbolAddress((void**)&p_xh,  g_xh);
    cudaGetSymbolAddress((void**)&p_wip, g_wip);
    cudaGetSymbolAddress((void**)&p_wop, g_wop);
    cudaGetSymbolAddress((void**)&p_wf1, g_wf1);
    cudaGetSymbolAddress((void**)&p_wf2, g_wf2);
    cudaGetSymbolAddress((void**)&p_yg,  g_yg);
    cudaGetSymbolAddress((void**)&p_xn,  g_xn);
    cudaGetSymbolAddress((void**)&p_min, g_min);

    cudaFuncSetAttribute(hgemm_kernel,
                         cudaFuncAttributeMaxDynamicSharedMemorySize, GEMM_SMEM_BYTES);

    // 0) fp16-round GEMM operands coming straight from inputs
    cvt_h_kernel<<<(ROWS * D_SZ / 4 + 255) / 256, 256>>>(x, p_xh, ROWS * D_SZ / 4);
    cvt_h_kernel<<<(D_IN_PROJ * D_SZ / 4 + 255) / 256, 256>>>(in_proj_w, p_wip, D_IN_PROJ * D_SZ / 4);
    cvt_h_kernel<<<(D_SZ * D_INNER / 4 + 255) / 256, 256>>>(out_proj_w, p_wop, D_SZ * D_INNER / 4);
    cvt_h_kernel<<<(H_MLP * D_SZ / 4 + 255) / 256, 256>>>(fc1_w, p_wf1, H_MLP * D_SZ / 4);
    cvt_h_kernel<<<(D_SZ * H_MLP2 / 4 + 255) / 256, 256>>>(fc2_w, p_wf2, D_SZ * H_MLP2 / 4);

    // 1) in_proj: zxbcdt[2048,4256] = xh @ wip^T
    {
        dim3 grid((D_IN_PROJ + 127) / 128, ROWS / 128, 1);
        hgemm_kernel<<<grid, 256, GEMM_SMEM_BYTES>>>(p_xh, p_wip, nullptr, p_zx,
                                                     ROWS, D_IN_PROJ, D_SZ, D_SZ);
    }
    // 2) dt/dA
    dt_kernel<<<(ROWS * NHEADS + 255) / 256, 256>>>(dt_bias, A_log);
    // 3) conv + silu
    conv_silu_kernel<<<(ROWS * CONV_DIM + 255) / 256, 256>>>(conv_w, conv_b);
    // 4) scan
    scan_kernel<<<B_SZ * NHEADS * 4, 1024>>>();
    // 5) gate + rms(ssm_norm)
    gate_rms_kernel<<<ROWS, 256>>>(Dp, ssm_norm_w);
    // 6) out_proj split-K=2, then x1 = x + sum parts
    {
        dim3 grid(D_SZ / 128, ROWS / 128, 2);
        hgemm_kernel<<<grid, 256, GEMM_SMEM_BYTES>>>(p_yg, p_wop, nullptr, p_part,
                                                     ROWS, D_SZ, D_INNER, D_INNER / 2);
        reduce_kernel<2><<<(ROWS * D_SZ / 4 + 255) / 256, 256>>>(p_part, x, p_x1, ROWS * D_SZ / 4);
    }
    // 7) rms
    rms_kernel<<<ROWS, 256>>>(rms_w);
    // 8) fc1: h1 = xn @ wf1^T
    {
        dim3 grid(H_MLP / 128, ROWS / 128, 1);
        hgemm_kernel<<<grid, 256, GEMM_SMEM_BYTES>>>(p_xn, p_wf1, nullptr, p_h1,
                                                     ROWS, H_MLP, D_SZ, D_SZ);
    }
    // 9) GLU
    glu_kernel<<<(ROWS * H_MLP2 + 255) / 256, 256>>>();
    // 10) fc2 split-K=4, then out = x1 + sum parts
    {
        dim3 grid(D_SZ / 128, ROWS / 128, 4);
        hgemm_kernel<<<grid, 256, GEMM_SMEM_BYTES>>>(p_min, p_wf2, nullptr, p_part,
                                                     ROWS, D_SZ, H_MLP2, H_MLP2 / 4);
        reduce_kernel<4><<<(ROWS * D_SZ / 4 + 255) / 256, 256>>>(p_part, p_x1, out, ROWS * D_SZ / 4);
    }
}

// round 7
// speedup vs baseline: 3.1916x; 1.2148x over previous
#include <cuda_runtime.h>
#include <cuda_fp16.h>
#include <cstdint>
#include <cstdio>

// ---------------- problem constants ----------------
#define B_SZ 2
#define S_SZ 1024
#define D_SZ 1024
#define D_INNER 2048
#define HEADDIM 64
#define NHEADS 32
#define D_STATE 64
#define D_CONV 4
#define CONV_DIM (D_INNER + 2 * D_STATE)                 // 2176
#define D_IN_PROJ (2 * D_INNER + 2 * D_STATE + NHEADS)   // 4256
#define H_MLP 8192
#define H_MLP2 4096
#define ROWS (B_SZ * S_SZ)                               // 2048

// ---------------- scratch (device globals; no allocation allowed) ----------------
__device__ float g_zxbcdt[ROWS * D_IN_PROJ];
__device__ float g_xbc[ROWS * CONV_DIM];
__device__ float2 g_dtda[ROWS * NHEADS];                 // packed (dt, dA)
__device__ float g_y[ROWS * D_INNER];
__device__ float g_x1[ROWS * D_SZ];
__device__ float g_h1[ROWS * H_MLP];
__device__ float g_part[4 * ROWS * D_SZ];                // split-K partials
// fp16 GEMM operands
__device__ __half g_xh [ROWS * D_SZ];
__device__ __half g_wip[D_IN_PROJ * D_SZ];
__device__ __half g_wop[D_SZ * D_INNER];
__device__ __half g_wf1[H_MLP * D_SZ];
__device__ __half g_wf2[D_SZ * H_MLP2];
__device__ __half g_yg [ROWS * D_INNER];
__device__ __half g_xn [ROWS * D_SZ];
__device__ __half g_min[ROWS * H_MLP2];

__device__ __forceinline__ float silu_f(float v) {
    return v / (1.f + __expf(-v));
}
__device__ __forceinline__ uint32_t smem_u32(const void* p) {
    uint32_t a;
    asm("{ .reg .u64 t; cvta.to.shared.u64 t, %1; cvt.u32.u64 %0, t; }" : "=r"(a) : "l"(p));
    return a;
}
__device__ __forceinline__ void cp_async16(uint32_t dst, const void* src) {
    asm volatile("cp.async.cg.shared.global [%0], [%1], 16;" :: "r"(dst), "l"(src));
}
#define CP_COMMIT() asm volatile("cp.async.commit_group;" ::: "memory")
#define CP_WAIT(n)  asm volatile("cp.async.wait_group %0;" :: "n"(n) : "memory")

// ---------------- pipelined fp16 mma.sync GEMM (ldmatrix fragments, optional split-K) ----------------
#define HPITCHW 20
#define ASTGW (128 * HPITCHW)
#define STGW  (2 * ASTGW)
#define NSTG  4
#define GEMM_SMEM_BYTES (NSTG * STGW * 4)   // 81920

__global__ __launch_bounds__(256, 2) void hgemm_kernel(
    const __half* __restrict__ A, const __half* __restrict__ W,
    const float* __restrict__ addend, float* __restrict__ C,
    int M, int N, int K, int kchunk)
{
    extern __shared__ uint32_t sm[];
    const uint32_t sb = smem_u32(sm);

    const int tid = threadIdx.x;
    const int bm = blockIdx.y * 128;
    const int bn = blockIdx.x * 128;
    const int kbeg = blockIdx.z * kchunk;
    const bool partial = (gridDim.z > 1);

    const int warp = tid >> 5;
    const int lane = tid & 31;
    const int g  = lane >> 2;
    const int t4 = lane & 3;
    const int warp_m = (warp >> 2) * 64;
    const int warp_n = (warp & 3) * 32;

    // ldmatrix per-lane byte offsets within a stage
    const uint32_t a_off =
        ((uint32_t)(warp_m + (lane & 7) + ((lane >> 3) & 1) * 8) * HPITCHW
         + ((lane >> 4) & 1) * 4) * 4;
    const int lb = lane & 15;
    const uint32_t b_off =
        ((uint32_t)(warp_n + (lb & 7)) * HPITCHW + ((lb >> 3) & 1) * 4) * 4;

    const int lr = tid >> 2;
    const int q  = tid & 3;

    const __half* Ap0 = A + (size_t)(bm + lr) * K + kbeg + q * 8;
    const __half* Ap1 = A + (size_t)(bm + 64 + lr) * K + kbeg + q * 8;
    int wr0 = bn + lr;      if (wr0 > N - 1) wr0 = N - 1;
    int wr1 = bn + 64 + lr; if (wr1 > N - 1) wr1 = N - 1;
    const __half* Wp0 = W + (size_t)wr0 * K + kbeg + q * 8;
    const __half* Wp1 = W + (size_t)wr1 * K + kbeg + q * 8;

    const uint32_t d0 = (uint32_t)lr * 80 + q * 16;
    const uint32_t d1 = d0 + 64 * 80;
    const int T = kchunk / 32;

    float acc[4][4][4];
#pragma unroll
    for (int i = 0; i < 4; i++)
#pragma unroll
        for (int j = 0; j < 4; j++)
#pragma unroll
            for (int r = 0; r < 4; r++) acc[i][j][r] = 0.f;

    auto load_stage = [&](int j) {
        if (j < T) {
            const uint32_t base = sb + (j & (NSTG - 1)) * (STGW * 4);
            const int ko = j * 32;
            cp_async16(base + d0, Ap0 + ko);
            cp_async16(base + d1, Ap1 + ko);
            cp_async16(base + ASTGW * 4 + d0, Wp0 + ko);
            cp_async16(base + ASTGW * 4 + d1, Wp1 + ko);
        }
        CP_COMMIT();
    };

    load_stage(0);
    load_stage(1);
    load_stage(2);

    for (int kt = 0; kt < T; kt++) {
        CP_WAIT(2);
        __syncthreads();
        load_stage(kt + 3);

        const uint32_t sA = sb + (kt & (NSTG - 1)) * (STGW * 4);
        const uint32_t sB = sA + ASTGW * 4;
#pragma unroll
        for (int kw = 0; kw < 16; kw += 8) {
            uint32_t af[4][4];
            uint32_t bf[4][2];
#pragma unroll
            for (int mt = 0; mt < 4; mt++) {
                const uint32_t addr = sA + a_off + (uint32_t)(mt * 16 * HPITCHW + kw) * 4;
                asm volatile(
                    "ldmatrix.sync.aligned.m8n8.x4.shared.b16 {%0,%1,%2,%3}, [%4];"
                    : "=r"(af[mt][0]), "=r"(af[mt][1]), "=r"(af[mt][2]), "=r"(af[mt][3])
                    : "r"(addr));
            }
#pragma unroll
            for (int nt = 0; nt < 4; nt++) {
                const uint32_t addr = sB + b_off + (uint32_t)(nt * 8 * HPITCHW + kw) * 4;
                asm volatile(
                    "ldmatrix.sync.aligned.m8n8.x2.shared.b16 {%0,%1}, [%2];"
                    : "=r"(bf[nt][0]), "=r"(bf[nt][1])
                    : "r"(addr));
            }
#pragma unroll
            for (int mt = 0; mt < 4; mt++)
#pragma unroll
                for (int nt = 0; nt < 4; nt++) {
                    asm volatile(
                        "mma.sync.aligned.m16n8k16.row.col.f32.f16.f16.f32 "
                        "{%0,%1,%2,%3}, {%4,%5,%6,%7}, {%8,%9}, {%0,%1,%2,%3};"
                        : "+f"(acc[mt][nt][0]), "+f"(acc[mt][nt][1]),
                          "+f"(acc[mt][nt][2]), "+f"(acc[mt][nt][3])
                        : "r"(af[mt][0]), "r"(af[mt][1]), "r"(af[mt][2]), "r"(af[mt][3]),
                          "r"(bf[nt][0]), "r"(bf[nt][1]));
                }
        }
    }

    float* Co = partial ? (C + (size_t)blockIdx.z * M * N) : C;

#pragma unroll
    for (int mt = 0; mt < 4; mt++) {
        const int row0 = bm + warp_m + mt * 16 + g;
#pragma unroll
        for (int nt = 0; nt < 4; nt++) {
            const int col = bn + warp_n + nt * 8 + 2 * t4;
            if (col < N) {
                float2 v0 = make_float2(acc[mt][nt][0], acc[mt][nt][1]);
                float2 v1 = make_float2(acc[mt][nt][2], acc[mt][nt][3]);
                if (!partial && addend) {
                    const float2 a0 = *reinterpret_cast<const float2*>(&addend[(size_t)row0 * N + col]);
                    const float2 a1 = *reinterpret_cast<const float2*>(&addend[(size_t)(row0 + 8) * N + col]);
                    v0.x += a0.x; v0.y += a0.y;
                    v1.x += a1.x; v1.y += a1.y;
                }
                *reinterpret_cast<float2*>(&Co[(size_t)row0 * N + col]) = v0;
                *reinterpret_cast<float2*>(&Co[(size_t)(row0 + 8) * N + col]) = v1;
            }
        }
    }
}

// ---------------- split-K reduction: out = addend + sum_z part[z] ----------------
template <int NSPLIT>
__global__ void reduce_kernel(const float* __restrict__ part,
                              const float* __restrict__ addend,
                              float* __restrict__ out, int n4)
{
    const int i = blockIdx.x * blockDim.x + threadIdx.x;
    if (i >= n4) return;
    float4 v = reinterpret_cast<const float4*>(addend)[i];
#pragma unroll
    for (int z = 0; z < NSPLIT; z++) {
        const float4 p = reinterpret_cast<const float4*>(part + (size_t)z * ROWS * D_SZ)[i];
        v.x += p.x; v.y += p.y; v.z += p.z; v.w += p.w;
    }
    reinterpret_cast<float4*>(out)[i] = v;
}

// ---------------- fp32 -> fp16 conversion ----------------
__global__ void cvt_h_kernel(const float* __restrict__ in, __half* __restrict__ out, int n4)
{
    const int i = blockIdx.x * blockDim.x + threadIdx.x;
    if (i >= n4) return;
    float4 v = reinterpret_cast<const float4*>(in)[i];
    __half2 h0 = __floats2half2_rn(v.x, v.y);
    __half2 h1 = __floats2half2_rn(v.z, v.w);
    *reinterpret_cast<uint2*>(out + (size_t)i * 4) =
        make_uint2(*reinterpret_cast<uint32_t*>(&h0), *reinterpret_cast<uint32_t*>(&h1));
}

// ---------------- causal depthwise conv (k=4) + bias + silu ----------------
__global__ void conv_silu_kernel(const float* __restrict__ conv_w,
                                 const float* __restrict__ conv_b)
{
    const int idx = blockIdx.x * blockDim.x + threadIdx.x;
    if (idx >= ROWS * CONV_DIM) return;
    const int c = idx % CONV_DIM;
    const int bs = idx / CONV_DIM;
    const int s = bs % S_SZ;
    const int b = bs / S_SZ;

    float acc = conv_b[c];
#pragma unroll
    for (int k = 0; k < D_CONV; k++) {
        const int ss = s - (D_CONV - 1) + k;
        if (ss >= 0)
            acc = fmaf(g_zxbcdt[(size_t)(b * S_SZ + ss) * D_IN_PROJ + D_INNER + c],
                       conv_w[c * D_CONV + k], acc);
    }
    g_xbc[idx] = silu_f(acc);
}

// ---------------- dt = softplus, dA = exp(-exp(A_log)*dt), packed ----------------
__global__ void dt_kernel(const float* __restrict__ dt_bias,
                          const float* __restrict__ A_log)
{
    const int idx = blockIdx.x * blockDim.x + threadIdx.x;
    if (idx >= ROWS * NHEADS) return;
    const int h = idx % NHEADS;
    const int r = idx / NHEADS;
    float x = g_zxbcdt[(size_t)r * D_IN_PROJ + (D_IN_PROJ - NHEADS) + h] + dt_bias[h];
    float dt = (x > 20.f) ? x : log1pf(expf(x));
    g_dtda[idx] = make_float2(dt, expf(-expf(A_log[h]) * dt));
}

// ---------------- SSM scan: warp-per-p, no block syncs, 4-step groups ----------------
// grid 256 = (b, h, pc of 16 p); block = 512 thr = 16 warps; warp w -> p = pc*16+w.
// Lane holds n = {2*lane, 2*lane+1}.
__global__ __launch_bounds__(512, 2) void scan_kernel()
{
    const int pc   = blockIdx.x & 3;
    const int h    = (blockIdx.x >> 2) & (NHEADS - 1);
    const int b    = blockIdx.x >> 7;
    const int w    = threadIdx.x >> 5;
    const int lane = threadIdx.x & 31;
    const int p    = pc * 16 + w;

    const float* rb = g_xbc + (size_t)(b * S_SZ) * CONV_DIM;
    const int xoff = h * HEADDIM + p;
    const float2* dd = g_dtda + (size_t)(b * S_SZ) * NHEADS + h;
    float* yo = g_y + ((size_t)b * S_SZ * NHEADS + h) * HEADDIM + p;

    float h0 = 0.f, h1 = 0.f;

    float2 Bv[2][4], Cv[2][4], Dv[2][4];
    float  Xv[2][4];

    auto ldgrp = [&](int grp, int buf) {
#pragma unroll
        for (int i = 0; i < 4; i++) {
            const int s = grp * 4 + i;
            const float* row = rb + (size_t)s * CONV_DIM;
            Bv[buf][i] = __ldg(reinterpret_cast<const float2*>(row + D_INNER) + lane);
            Cv[buf][i] = __ldg(reinterpret_cast<const float2*>(row + D_INNER + D_STATE) + lane);
            Xv[buf][i] = __ldg(row + xoff);
            Dv[buf][i] = __ldg(dd + (size_t)s * NHEADS);
        }
    };

    ldgrp(0, 0);
    const int NG = S_SZ / 4;
    for (int grp = 0; grp < NG; grp++) {
        const int cur = grp & 1;
        if (grp + 1 < NG) ldgrp(grp + 1, cur ^ 1);

        float part[4];
#pragma unroll
        for (int i = 0; i < 4; i++) {
            const float c = Dv[cur][i].x * Xv[cur][i];
            h0 = fmaf(h0, Dv[cur][i].y, c * Bv[cur][i].x);
            h1 = fmaf(h1, Dv[cur][i].y, c * Bv[cur][i].y);
            part[i] = fmaf(h1, Cv[cur][i].y, h0 * Cv[cur][i].x);
        }
#pragma unroll
        for (int o = 16; o > 0; o >>= 1) {
#pragma unroll
            for (int i = 0; i < 4; i++)
                part[i] += __shfl_xor_sync(0xffffffffu, part[i], o);
        }
        if (lane == 0) {
#pragma unroll
            for (int i = 0; i < 4; i++)
                yo[(size_t)(grp * 4 + i) * (NHEADS * HEADDIM)] = part[i];
        }
    }
}

// ---------------- gate: yg = rms((y + D*xs) * silu(z)) * w  -> fp16 ----------------
__global__ __launch_bounds__(256) void gate_rms_kernel(const float* __restrict__ Dp,
                                                       const float* __restrict__ normw)
{
    const int row = blockIdx.x;
    const int tid = threadIdx.x;

    const float* yr = g_y      + (size_t)row * D_INNER;
    const float* xb = g_xbc    + (size_t)row * CONV_DIM;
    const float* zr = g_zxbcdt + (size_t)row * D_IN_PROJ;

    float vals[8];
    float ss = 0.f;
#pragma unroll
    for (int i = 0; i < 8; i++) {
        const int c = tid + i * 256;
        float v = fmaf(Dp[c >> 6], xb[c], yr[c]);
        v *= silu_f(zr[c]);
        vals[i] = v;
        ss = fmaf(v, v, ss);
    }
    __shared__ float red[32];
#pragma unroll
    for (int o = 16; o > 0; o >>= 1) ss += __shfl_down_sync(0xffffffffu, ss, o);
    if ((tid & 31) == 0) red[tid >> 5] = ss;
    __syncthreads();
    if (tid < 32) {
        float v = (tid < 8) ? red[tid] : 0.f;
#pragma unroll
        for (int o = 4; o > 0; o >>= 1) v += __shfl_down_sync(0xffffffffu, v, o);
        if (tid == 0) red[0] = v;
    }
    __syncthreads();
    const float inv = rsqrtf(red[0] / (float)D_INNER + 1e-5f);
#pragma unroll
    for (int i = 0; i < 8; i++) {
        const int c = tid + i * 256;
        g_yg[(size_t)row * D_INNER + c] = __float2half_rn(vals[i] * inv * normw[c]);
    }
}

// ---------------- rms over D: xn = rms(x1) * rms_w  -> fp16 ----------------
__global__ __launch_bounds__(256) void rms_kernel(const float* __restrict__ w)
{
    const int row = blockIdx.x;
    const int tid = threadIdx.x;
    const float* xr = g_x1 + (size_t)row * D_SZ;

    float vals[4];
    float ss = 0.f;
#pragma unroll
    for (int i = 0; i < 4; i++) {
        const int c = tid + i * 256;
        vals[i] = xr[c];
        ss = fmaf(vals[i], vals[i], ss);
    }
    __shared__ float red[32];
#pragma unroll
    for (int o = 16; o > 0; o >>= 1) ss += __shfl_down_sync(0xffffffffu, ss, o);
    if ((tid & 31) == 0) red[tid >> 5] = ss;
    __syncthreads();
    if (tid < 32) {
        float v = (tid < 8) ? red[tid] : 0.f;
#pragma unroll
        for (int o = 4; o > 0; o >>= 1) v += __shfl_down_sync(0xffffffffu, v, o);
        if (tid == 0) red[0] = v;
    }
    __syncthreads();
    const float inv = rsqrtf(red[0] / (float)D_SZ + 1e-5f);
#pragma unroll
    for (int i = 0; i < 4; i++) {
        const int c = tid + i * 256;
        g_xn[(size_t)row * D_SZ + c] = __float2half_rn(vals[i] * inv * w[c]);
    }
}

// ---------------- GLU: m_in = a * silu(g)  -> fp16 ----------------
__global__ void glu_kernel()
{
    const int idx = blockIdx.x * blockDim.x + threadIdx.x;
    if (idx >= ROWS * H_MLP2) return;
    const int j = idx % H_MLP2;
    const int r = idx / H_MLP2;
    const float a = g_h1[(size_t)r * H_MLP + j];
    const float g = g_h1[(size_t)r * H_MLP + H_MLP2 + j];
    g_min[idx] = __float2half_rn(a * silu_f(g));
}

// ---------------- launch ----------------
extern "C" void kernel_launch(void* const* d_in, const int* in_sizes, int n_in,
                              void* d_out, int out_size)
{
    const float* x          = (const float*)d_in[0];
    const float* in_proj_w  = (const float*)d_in[1];
    const float* conv_w     = (const float*)d_in[2];
    const float* conv_b     = (const float*)d_in[3];
    const float* dt_bias    = (const float*)d_in[4];
    const float* A_log      = (const float*)d_in[5];
    const float* Dp         = (const float*)d_in[6];
    const float* ssm_norm_w = (const float*)d_in[7];
    const float* out_proj_w = (const float*)d_in[8];
    const float* rms_w      = (const float*)d_in[9];
    const float* fc1_w      = (const float*)d_in[10];
    const float* fc2_w      = (const float*)d_in[11];
    float* out = (float*)d_out;

    float *p_zx, *p_x1, *p_h1, *p_part;
    __half *p_xh, *p_wip, *p_wop, *p_wf1, *p_wf2, *p_yg, *p_xn, *p_min;
    cudaGetSymbolAddress((void**)&p_zx,  g_zxbcdt);
    cudaGetSymbolAddress((void**)&p_x1,  g_x1);
    cudaGetSymbolAddress((void**)&p_h1,  g_h1);
    cudaGetSymbolAddress((void**)&p_part, g_part);
    cudaGetSymbolAddress((void**)&p_xh,  g_xh);
    cudaGetSymbolAddress((void**)&p_wip, g_wip);
    cudaGetSymbolAddress((void**)&p_wop, g_wop);
    cudaGetSymbolAddress((void**)&p_wf1, g_wf1);
    cudaGetSymbolAddress((void**)&p_wf2, g_wf2);
    cudaGetSymbolAddress((void**)&p_yg,  g_yg);
    cudaGetSymbolAddress((void**)&p_xn,  g_xn);
    cudaGetSymbolAddress((void**)&p_min, g_min);

    cudaFuncSetAttribute(hgemm_kernel,
                         cudaFuncAttributeMaxDynamicSharedMemorySize, GEMM_SMEM_BYTES);

    // 0) fp16-round GEMM operands coming straight from inputs
    cvt_h_kernel<<<(ROWS * D_SZ / 4 + 255) / 256, 256>>>(x, p_xh, ROWS * D_SZ / 4);
    cvt_h_kernel<<<(D_IN_PROJ * D_SZ / 4 + 255) / 256, 256>>>(in_proj_w, p_wip, D_IN_PROJ * D_SZ / 4);
    cvt_h_kernel<<<(D_SZ * D_INNER / 4 + 255) / 256, 256>>>(out_proj_w, p_wop, D_SZ * D_INNER / 4);
    cvt_h_kernel<<<(H_MLP * D_SZ / 4 + 255) / 256, 256>>>(fc1_w, p_wf1, H_MLP * D_SZ / 4);
    cvt_h_kernel<<<(D_SZ * H_MLP2 / 4 + 255) / 256, 256>>>(fc2_w, p_wf2, D_SZ * H_MLP2 / 4);

    // 1) in_proj: zxbcdt[2048,4256] = xh @ wip^T
    {
        dim3 grid((D_IN_PROJ + 127) / 128, ROWS / 128, 1);
        hgemm_kernel<<<grid, 256, GEMM_SMEM_BYTES>>>(p_xh, p_wip, nullptr, p_zx,
                                                     ROWS, D_IN_PROJ, D_SZ, D_SZ);
    }
    // 2) dt/dA (packed)
    dt_kernel<<<(ROWS * NHEADS + 255) / 256, 256>>>(dt_bias, A_log);
    // 3) conv + silu
    conv_silu_kernel<<<(ROWS * CONV_DIM + 255) / 256, 256>>>(conv_w, conv_b);
    // 4) scan (warp-autonomous)
    scan_kernel<<<B_SZ * NHEADS * 4, 512>>>();
    // 5) gate + rms(ssm_norm)
    gate_rms_kernel<<<ROWS, 256>>>(Dp, ssm_norm_w);
    // 6) out_proj split-K=2, then x1 = x + sum parts
    {
        dim3 grid(D_SZ / 128, ROWS / 128, 2);
        hgemm_kernel<<<grid, 256, GEMM_SMEM_BYTES>>>(p_yg, p_wop, nullptr, p_part,
                                                     ROWS, D_SZ, D_INNER, D_INNER / 2);
        reduce_kernel<2><<<(ROWS * D_SZ / 4 + 255) / 256, 256>>>(p_part, x, p_x1, ROWS * D_SZ / 4);
    }
    // 7) rms
    rms_kernel<<<ROWS, 256>>>(rms_w);
    // 8) fc1: h1 = xn @ wf1^T
    {
        dim3 grid(H_MLP / 128, ROWS / 128, 1);
        hgemm_kernel<<<grid, 256, GEMM_SMEM_BYTES>>>(p_xn, p_wf1, nullptr, p_h1,
                                                     ROWS, H_MLP, D_SZ, D_SZ);
    }
    // 9) GLU
    glu_kernel<<<(ROWS * H_MLP2 + 255) / 256, 256>>>();
    // 10) fc2 split-K=4, then out = x1 + sum parts
    {
        dim3 grid(D_SZ / 128, ROWS / 128, 4);
        hgemm_kernel<<<grid, 256, GEMM_SMEM_BYTES>>>(p_min, p_wf2, nullptr, p_part,
                                                     ROWS, D_SZ, H_MLP2, H_MLP2 / 4);
        reduce_kernel<4><<<(ROWS * D_SZ / 4 + 255) / 256, 256>>>(p_part, p_x1, out, ROWS * D_SZ / 4);
    }
}